// round 12
// baseline (speedup 1.0000x reference)
#include <cuda_runtime.h>
#include <cuda_bf16.h>
#include <math.h>
#include <stdint.h>

// Problem constants (fixed by the dataset)
#define B_  4
#define Q_  1024
#define D_  1024
#define N_  16
#define DH_ 64
#define DI_ 4096
#define BQ  (B_ * Q_)      // 4096
#define D3  (3 * D_)       // 3072

// ---------------- scratch (static device globals; no allocation) -------------
__device__ float g_heads[BQ * D3];   // 48 MB
__device__ float g_rk   [Q_ * D_];   //  4 MB
__device__ float g_av   [BQ * D_];   // 16 MB
__device__ float g_tmp  [BQ * D_];   // 16 MB
__device__ float g_out1 [BQ * D_];   // 16 MB
__device__ float g_ff1  [BQ * DI_];  // 64 MB

// ---------------- helpers ------------------------------------------------------
__device__ __forceinline__ uint32_t f2tf32(float x) {
    uint32_t r;
    asm("cvt.rna.tf32.f32 %0, %1;" : "=r"(r) : "f"(x));
    return r;
}
__device__ __forceinline__ void mma_tf32(float* d, const uint32_t* a,
                                         const uint32_t* b) {
    asm volatile(
        "mma.sync.aligned.m16n8k8.row.col.f32.tf32.tf32.f32 "
        "{%0,%1,%2,%3}, {%4,%5,%6,%7}, {%8,%9}, {%0,%1,%2,%3};"
        : "+f"(d[0]), "+f"(d[1]), "+f"(d[2]), "+f"(d[3])
        : "r"(a[0]), "r"(a[1]), "r"(a[2]), "r"(a[3]), "r"(b[0]), "r"(b[1]));
}

// ---- fragment-major smem addressing ----
// A tiles 16x8 (128 words); inner word f*4+e, conflict-free LDS.128.
__device__ __forceinline__ int a_inner(int row, int k) {
    int ld = ((row & 7) << 2) | (k & 3);
    int e  = ((k & 4) >> 1) | ((row & 8) >> 3);
    int f  = ld ^ (ld >> 3);
    return f * 4 + e;
}
// A for 128-row CTA tile (8 mtiles/ktile)
__device__ __forceinline__ int a_word8(int row, int k) {
    return (((k >> 3) << 3) | (row >> 4)) * 128 + a_inner(row, k);
}
// A for 256-row CTA tile (16 mtiles/ktile)
__device__ __forceinline__ int a_word16(int row, int k) {
    return (((k >> 3) << 4) | (row >> 4)) * 128 + a_inner(row, k);
}
// B tiles 8x8 (64 words, stride 72): 16 ntiles/ktile (128 cols)
__device__ __forceinline__ int b_word(int row, int k) {
    int ld = ((row & 7) << 2) | (k & 3);
    int e  = (k & 4) >> 2;
    int h  = ld ^ (ld >> 3);
    return ((k >> 3) * 16 + (row >> 3)) * 72 + h * 2 + e;
}

// ---------------- big GEMM: 256x128 CTA tile, warp tile 64x64 ------------------
// 256 threads (8 warps 4x2), BK=16, register-prefetch double buffer.
// smem: sA 2x4096 w | sB 2x2304 w  = 50 KB dynamic.
#define GB_SMEM ((2 * 4096 + 2 * 2304) * 4)

template<bool BIAS, bool RELU>
__global__ void __launch_bounds__(256, 1) gemm_big(
    const float* __restrict__ A, const float* __restrict__ W,
    const float* __restrict__ bias, float* __restrict__ C,
    int M, int K, int ldc)
{
    extern __shared__ uint32_t smw[];
    uint32_t* sA = smw;            // [2][4096]
    uint32_t* sB = smw + 8192;     // [2][2304]

    const int t    = threadIdx.x;
    const int m0   = blockIdx.y * 256;
    const int n0   = blockIdx.x * 128;
    const int lane = t & 31;
    const int w    = t >> 5;
    const int g    = lane >> 2;
    const int t4   = lane & 3;
    const int wr   = w >> 1;           // 0..3 -> m offset wr*64
    const int wcol = w & 1;            // 0..1 -> n offset wcol*64
    const int fl   = lane ^ (lane >> 3);
    const int brow = t >> 1;           // B load row (0..127)
    const int bkq  = (t & 1) * 8;      // B load k offset

    const float* Ap = A + (size_t)(m0 + t) * K;          // 1 row / thread
    const float* Wp = W + (size_t)(n0 + brow) * K + bkq;

    float acc[4][8][4];
    #pragma unroll
    for (int mt = 0; mt < 4; mt++)
        #pragma unroll
        for (int nt = 0; nt < 8; nt++)
            #pragma unroll
            for (int e = 0; e < 4; e++) acc[mt][nt][e] = 0.f;

    float4 pa[4], pw[2];
    #pragma unroll
    for (int u = 0; u < 4; u++) pa[u] = *(const float4*)(Ap + u * 4);
    pw[0] = *(const float4*)Wp;
    pw[1] = *(const float4*)(Wp + 4);

    auto store_stage = [&](int bf_) {
        uint32_t* dA = sA + bf_ * 4096;
        uint32_t* dB = sB + bf_ * 2304;
        float va[16] = {pa[0].x, pa[0].y, pa[0].z, pa[0].w,
                        pa[1].x, pa[1].y, pa[1].z, pa[1].w,
                        pa[2].x, pa[2].y, pa[2].z, pa[2].w,
                        pa[3].x, pa[3].y, pa[3].z, pa[3].w};
        #pragma unroll
        for (int u = 0; u < 16; u++) dA[a_word16(t, u)] = f2tf32(va[u]);
        float vb[8] = {pw[0].x, pw[0].y, pw[0].z, pw[0].w,
                       pw[1].x, pw[1].y, pw[1].z, pw[1].w};
        #pragma unroll
        for (int u = 0; u < 8; u++) dB[b_word(brow, bkq + u)] = f2tf32(vb[u]);
    };

    store_stage(0);
    __syncthreads();

    int buf = 0;
    for (int k0 = 0; k0 < K; k0 += 16) {
        const bool has_next = (k0 + 16 < K);
        if (has_next) {
            #pragma unroll
            for (int u = 0; u < 4; u++)
                pa[u] = *(const float4*)(Ap + k0 + 16 + u * 4);
            pw[0] = *(const float4*)(Wp + k0 + 16);
            pw[1] = *(const float4*)(Wp + k0 + 20);
        }

        #pragma unroll
        for (int kk = 0; kk < 2; kk++) {
            uint4 af[4];
            uint2 bfr[8];
            #pragma unroll
            for (int mt = 0; mt < 4; mt++)
                af[mt] = *(const uint4*)
                    &sA[buf * 4096 + (kk * 16 + wr * 4 + mt) * 128 + fl * 4];
            #pragma unroll
            for (int nt = 0; nt < 8; nt++)
                bfr[nt] = *(const uint2*)
                    &sB[buf * 2304 + (kk * 16 + wcol * 8 + nt) * 72 + fl * 2];
            #pragma unroll
            for (int mt = 0; mt < 4; mt++)
                #pragma unroll
                for (int nt = 0; nt < 8; nt++)
                    mma_tf32(acc[mt][nt], (const uint32_t*)&af[mt],
                             (const uint32_t*)&bfr[nt]);
        }

        if (has_next) {
            buf ^= 1;
            store_stage(buf);
            __syncthreads();
        }
    }

    // ---- epilogue ----
    #pragma unroll
    for (int mt = 0; mt < 4; mt++) {
        const int row = m0 + wr * 64 + mt * 16 + g;
        #pragma unroll
        for (int nt = 0; nt < 8; nt++) {
            const int col = n0 + wcol * 64 + nt * 8 + 2 * t4;
            float b0v = BIAS ? bias[col]     : 0.f;
            float b1v = BIAS ? bias[col + 1] : 0.f;
            float x0 = acc[mt][nt][0] + b0v;
            float x1 = acc[mt][nt][1] + b1v;
            float x2 = acc[mt][nt][2] + b0v;
            float x3 = acc[mt][nt][3] + b1v;
            if (RELU) {
                x0 = fmaxf(x0, 0.f); x1 = fmaxf(x1, 0.f);
                x2 = fmaxf(x2, 0.f); x3 = fmaxf(x3, 0.f);
            }
            *(float2*)&C[(size_t)row * ldc + col]       = make_float2(x0, x1);
            *(float2*)&C[(size_t)(row + 8) * ldc + col] = make_float2(x2, x3);
        }
    }
}

// ---------------- small GEMM (rk): 128x128, R8 structure ----------------------
__global__ void __launch_bounds__(256, 2) gemm_sm(
    const float* __restrict__ A, const float* __restrict__ W,
    float* __restrict__ C, int K, int ldc)
{
    __shared__ uint32_t sAh[2][2048];
    __shared__ uint32_t sWh[2][2304];

    const int t    = threadIdx.x;
    const int m0   = blockIdx.y * 128;
    const int n0   = blockIdx.x * 128;
    const int lane = t & 31;
    const int w    = t >> 5;
    const int g    = lane >> 2;
    const int t4   = lane & 3;
    const int wm   = (w >> 1) * 32;
    const int wn   = (w & 1) * 64;
    const int mt0  = (w >> 1) * 2;
    const int nt0  = (w & 1) * 8;
    const int fl   = lane ^ (lane >> 3);
    const int lrow = t >> 1;
    const int lkq  = (t & 1) * 8;

    const float* Ap = A + (size_t)(m0 + lrow) * K + lkq;
    const float* Wp = W + (size_t)(n0 + lrow) * K + lkq;

    float acc[2][8][4];
    #pragma unroll
    for (int mt = 0; mt < 2; mt++)
        #pragma unroll
        for (int nt = 0; nt < 8; nt++)
            #pragma unroll
            for (int e = 0; e < 4; e++) acc[mt][nt][e] = 0.f;

    float4 pa0 = *(const float4*)Ap;
    float4 pa1 = *(const float4*)(Ap + 4);
    float4 pw0 = *(const float4*)Wp;
    float4 pw1 = *(const float4*)(Wp + 4);

    auto store_stage = [&](int bf_, float4 a0, float4 a1, float4 w0, float4 w1) {
        float va[8] = {a0.x, a0.y, a0.z, a0.w, a1.x, a1.y, a1.z, a1.w};
        float vw[8] = {w0.x, w0.y, w0.z, w0.w, w1.x, w1.y, w1.z, w1.w};
        #pragma unroll
        for (int u = 0; u < 8; u++) {
            const int k = lkq + u;
            sAh[bf_][a_word8(lrow, k)] = f2tf32(va[u]);
            sWh[bf_][b_word(lrow, k)]  = f2tf32(vw[u]);
        }
    };

    store_stage(0, pa0, pa1, pw0, pw1);
    __syncthreads();

    int buf = 0;
    for (int k0 = 0; k0 < K; k0 += 16) {
        const bool has_next = (k0 + 16 < K);
        if (has_next) {
            pa0 = *(const float4*)(Ap + k0 + 16);
            pa1 = *(const float4*)(Ap + k0 + 20);
            pw0 = *(const float4*)(Wp + k0 + 16);
            pw1 = *(const float4*)(Wp + k0 + 20);
        }
        #pragma unroll
        for (int kk = 0; kk < 2; kk++) {
            uint4 af[2];
            uint2 bfr[8];
            #pragma unroll
            for (int mt = 0; mt < 2; mt++)
                af[mt] = *(const uint4*)&sAh[buf][(kk * 8 + mt0 + mt) * 128 + fl * 4];
            #pragma unroll
            for (int nt = 0; nt < 8; nt++)
                bfr[nt] = *(const uint2*)&sWh[buf][(kk * 16 + nt0 + nt) * 72 + fl * 2];
            #pragma unroll
            for (int mt = 0; mt < 2; mt++)
                #pragma unroll
                for (int nt = 0; nt < 8; nt++)
                    mma_tf32(acc[mt][nt], (const uint32_t*)&af[mt],
                             (const uint32_t*)&bfr[nt]);
        }
        if (has_next) {
            buf ^= 1;
            store_stage(buf, pa0, pa1, pw0, pw1);
            __syncthreads();
        }
    }

    #pragma unroll
    for (int mt = 0; mt < 2; mt++) {
        const int row = m0 + wm + mt * 16 + g;
        #pragma unroll
        for (int nt = 0; nt < 8; nt++) {
            const int col = n0 + wn + nt * 8 + 2 * t4;
            *(float2*)&C[(size_t)row * ldc + col] =
                make_float2(acc[mt][nt][0], acc[mt][nt][1]);
            *(float2*)&C[(size_t)(row + 8) * ldc + col] =
                make_float2(acc[mt][nt][2], acc[mt][nt][3]);
        }
    }
}

// ---------------- MMA flash attention ------------------------------------------
__device__ __forceinline__ int bw8(int nn, int k) {
    int ld = ((nn & 7) << 2) | (k & 3);
    int e  = (k & 4) >> 2;
    int h  = ld ^ (ld >> 3);
    return ((k >> 3) * 8 + (nn >> 3)) * 72 + h * 2 + e;
}
__device__ __forceinline__ int bw16(int nn, int k) {
    int ld = ((nn & 7) << 2) | (k & 3);
    int e  = (k & 4) >> 2;
    int h  = ld ^ (ld >> 3);
    return ((k >> 3) * 16 + (nn >> 3)) * 72 + h * 2 + e;
}
__device__ __forceinline__ int aw4(int row, int k) {
    int ld = ((row & 7) << 2) | (k & 3);
    int e  = ((k & 4) >> 1) | ((row & 8) >> 3);
    int f  = ld ^ (ld >> 3);
    return ((k >> 3) * 4 + (row >> 4)) * 128 + f * 4 + e;
}

#define ATT_WORDS (4608 + 4608 + 9216 + 8448 + 256)
#define ATT_SMEM  (ATT_WORDS * 4)

__global__ void __launch_bounds__(256, 1) attn_mma(
    const float* __restrict__ heads, const float* __restrict__ rk,
    const float* __restrict__ rwb, const float* __restrict__ rrb,
    float* __restrict__ av)
{
    extern __shared__ uint32_t smw[];
    uint32_t* sK  = smw;
    uint32_t* sV  = sK + 4608;
    uint32_t* sB  = sV + 4608;
    float*    sBD = (float*)(sB + 9216);
    uint32_t* sP  = (uint32_t*)sBD;
    float*    red = sBD + 8448;

    const int i0   = (gridDim.x - 1 - blockIdx.x) * 64;
    const int n    = blockIdx.y;
    const int b    = blockIdx.z;
    const int t    = threadIdx.x;
    const int lane = t & 31;
    const int w    = t >> 5;
    const int wr   = w & 3;
    const int wc   = w >> 2;
    const int g    = lane >> 2;
    const int t4   = lane & 3;
    const int fl   = lane ^ (lane >> 3);

    uint32_t qw[8][4], qr[8][4];
    {
        const float* qb = heads + (size_t)(b * Q_ + i0 + wr * 16 + g) * D3 + n * DH_;
        const float* wb = rwb + n * DH_;
        const float* rb = rrb + n * DH_;
        #pragma unroll
        for (int kt = 0; kt < 8; kt++) {
            const int c0 = kt * 8 + t4, c1 = c0 + 4;
            float q00 = qb[c0], q01 = qb[c1];
            float q10 = qb[8 * D3 + c0], q11 = qb[8 * D3 + c1];
            qw[kt][0] = f2tf32(q00 + wb[c0]);
            qw[kt][1] = f2tf32(q10 + wb[c0]);
            qw[kt][2] = f2tf32(q01 + wb[c1]);
            qw[kt][3] = f2tf32(q11 + wb[c1]);
            qr[kt][0] = f2tf32(q00 + rb[c0]);
            qr[kt][1] = f2tf32(q10 + rb[c0]);
            qr[kt][2] = f2tf32(q01 + rb[c1]);
            qr[kt][3] = f2tf32(q11 + rb[c1]);
        }
    }

    float O[4][4];
    #pragma unroll
    for (int nt = 0; nt < 4; nt++)
        #pragma unroll
        for (int e = 0; e < 4; e++) O[nt][e] = 0.f;
    float m0r = -1e30f, m1r = -1e30f, l0r = 0.f, l1r = 0.f;

    const int di0 = wr * 16 + g;
    const int di1 = di0 + 8;

    for (int j0 = 0; j0 <= i0; j0 += 64) {
        __syncthreads();

        {
            const int jrow = t >> 2, d0 = (t & 3) * 16;
            const float* kp = heads + (size_t)(b * Q_ + j0 + jrow) * D3 + D_ + n * DH_ + d0;
            const float* vp = kp + D_;
            #pragma unroll
            for (int u = 0; u < 16; u += 4) {
                float4 kv = *(const float4*)(kp + u);
                float4 vv = *(const float4*)(vp + u);
                const int d = d0 + u;
                sK[bw8(jrow, d + 0)] = f2tf32(kv.x);
                sK[bw8(jrow, d + 1)] = f2tf32(kv.y);
                sK[bw8(jrow, d + 2)] = f2tf32(kv.z);
                sK[bw8(jrow, d + 3)] = f2tf32(kv.w);
                sV[bw8(d + 0, jrow)] = f2tf32(vv.x);
                sV[bw8(d + 1, jrow)] = f2tf32(vv.y);
                sV[bw8(d + 2, jrow)] = f2tf32(vv.z);
                sV[bw8(d + 3, jrow)] = f2tf32(vv.w);
            }
        }
        {
            const int lr_ = t >> 1, d0 = (t & 1) * 32;
            int grow = (Q_ - 64 - i0 + j0) + lr_;
            if (grow > Q_ - 1) grow = Q_ - 1;
            const float* rp = rk + (size_t)grow * D_ + n * DH_ + d0;
            #pragma unroll
            for (int u = 0; u < 32; u += 4) {
                float4 rv = *(const float4*)(rp + u);
                const int d = d0 + u;
                sB[bw16(lr_, d + 0)] = f2tf32(rv.x);
                sB[bw16(lr_, d + 1)] = f2tf32(rv.y);
                sB[bw16(lr_, d + 2)] = f2tf32(rv.z);
                sB[bw16(lr_, d + 3)] = f2tf32(rv.w);
            }
        }
        __syncthreads();

        {
            float bd[8][4];
            #pragma unroll
            for (int nt = 0; nt < 8; nt++)
                #pragma unroll
                for (int e = 0; e < 4; e++) bd[nt][e] = 0.f;
            #pragma unroll
            for (int kt = 0; kt < 8; kt++) {
                uint2 bf[8];
                #pragma unroll
                for (int nt = 0; nt < 8; nt++)
                    bf[nt] = *(const uint2*)&sB[(kt * 16 + wc * 8 + nt) * 72 + fl * 2];
                #pragma unroll
                for (int nt = 0; nt < 8; nt++)
                    mma_tf32(bd[nt], qr[kt], (const uint32_t*)&bf[nt]);
            }
            #pragma unroll
            for (int nt = 0; nt < 8; nt++) {
                const int lc = wc * 64 + nt * 8 + 2 * t4;
                sBD[di0 * 132 + lc]     = bd[nt][0];
                sBD[di0 * 132 + lc + 1] = bd[nt][1];
                sBD[di1 * 132 + lc]     = bd[nt][2];
                sBD[di1 * 132 + lc + 1] = bd[nt][3];
            }
        }
        __syncthreads();

        float p[4][4];
        {
            float ac[4][4];
            #pragma unroll
            for (int nt = 0; nt < 4; nt++)
                #pragma unroll
                for (int e = 0; e < 4; e++) ac[nt][e] = 0.f;
            #pragma unroll
            for (int kt = 0; kt < 8; kt++) {
                uint2 kf[4];
                #pragma unroll
                for (int nt = 0; nt < 4; nt++)
                    kf[nt] = *(const uint2*)&sK[(kt * 8 + wc * 4 + nt) * 72 + fl * 2];
                #pragma unroll
                for (int nt = 0; nt < 4; nt++)
                    mma_tf32(ac[nt], qw[kt], (const uint32_t*)&kf[nt]);
            }
            const bool diag = (j0 == i0);
            #pragma unroll
            for (int nt = 0; nt < 4; nt++) {
                const int dj = wc * 32 + nt * 8 + 2 * t4;
                float v00 = (ac[nt][0] + sBD[di0 * 132 + 63 - di0 + dj])     * 0.125f;
                float v01 = (ac[nt][1] + sBD[di0 * 132 + 63 - di0 + dj + 1]) * 0.125f;
                float v10 = (ac[nt][2] + sBD[di1 * 132 + 63 - di1 + dj])     * 0.125f;
                float v11 = (ac[nt][3] + sBD[di1 * 132 + 63 - di1 + dj + 1]) * 0.125f;
                if (diag) {
                    if (dj     > di0) v00 = -1e30f;
                    if (dj + 1 > di0) v01 = -1e30f;
                    if (dj     > di1) v10 = -1e30f;
                    if (dj + 1 > di1) v11 = -1e30f;
                }
                p[nt][0] = v00; p[nt][1] = v01; p[nt][2] = v10; p[nt][3] = v11;
            }
        }

        {
            float mx0 = -1e30f, mx1 = -1e30f;
            #pragma unroll
            for (int nt = 0; nt < 4; nt++) {
                mx0 = fmaxf(mx0, fmaxf(p[nt][0], p[nt][1]));
                mx1 = fmaxf(mx1, fmaxf(p[nt][2], p[nt][3]));
            }
            mx0 = fmaxf(mx0, __shfl_xor_sync(0xffffffffu, mx0, 1));
            mx0 = fmaxf(mx0, __shfl_xor_sync(0xffffffffu, mx0, 2));
            mx1 = fmaxf(mx1, __shfl_xor_sync(0xffffffffu, mx1, 1));
            mx1 = fmaxf(mx1, __shfl_xor_sync(0xffffffffu, mx1, 2));
            if (t4 == 0) {
                red[wc * 64 + di0] = mx0;
                red[wc * 64 + di1] = mx1;
            }
        }
        __syncthreads();

        const float mn0 = fmaxf(m0r, fmaxf(red[di0], red[64 + di0]));
        const float mn1 = fmaxf(m1r, fmaxf(red[di1], red[64 + di1]));
        const float fac0 = __expf(m0r - mn0);
        const float fac1 = __expf(m1r - mn1);
        m0r = mn0; m1r = mn1;

        {
            float s0 = 0.f, s1 = 0.f;
            #pragma unroll
            for (int nt = 0; nt < 4; nt++) {
                p[nt][0] = __expf(p[nt][0] - mn0);
                p[nt][1] = __expf(p[nt][1] - mn0);
                p[nt][2] = __expf(p[nt][2] - mn1);
                p[nt][3] = __expf(p[nt][3] - mn1);
                s0 += p[nt][0] + p[nt][1];
                s1 += p[nt][2] + p[nt][3];
            }
            s0 += __shfl_xor_sync(0xffffffffu, s0, 1);
            s0 += __shfl_xor_sync(0xffffffffu, s0, 2);
            s1 += __shfl_xor_sync(0xffffffffu, s1, 1);
            s1 += __shfl_xor_sync(0xffffffffu, s1, 2);
            if (t4 == 0) {
                red[128 + wc * 64 + di0] = s0;
                red[128 + wc * 64 + di1] = s1;
            }
        }
        __syncthreads();

        l0r = l0r * fac0 + red[128 + di0] + red[128 + 64 + di0];
        l1r = l1r * fac1 + red[128 + di1] + red[128 + 64 + di1];
        #pragma unroll
        for (int nt = 0; nt < 4; nt++) {
            O[nt][0] *= fac0; O[nt][1] *= fac0;
            O[nt][2] *= fac1; O[nt][3] *= fac1;
        }

        #pragma unroll
        for (int nt = 0; nt < 4; nt++) {
            const int dj = wc * 32 + nt * 8 + 2 * t4;
            sP[aw4(di0, dj)]     = f2tf32(p[nt][0]);
            sP[aw4(di0, dj + 1)] = f2tf32(p[nt][1]);
            sP[aw4(di1, dj)]     = f2tf32(p[nt][2]);
            sP[aw4(di1, dj + 1)] = f2tf32(p[nt][3]);
        }
        __syncthreads();

        #pragma unroll
        for (int kt = 0; kt < 8; kt++) {
            uint4 af = *(const uint4*)&sP[(kt * 4 + wr) * 128 + fl * 4];
            uint2 vf[4];
            #pragma unroll
            for (int nt = 0; nt < 4; nt++)
                vf[nt] = *(const uint2*)&sV[(kt * 8 + wc * 4 + nt) * 72 + fl * 2];
            #pragma unroll
            for (int nt = 0; nt < 4; nt++)
                mma_tf32(O[nt], (const uint32_t*)&af, (const uint32_t*)&vf[nt]);
        }
    }

    const float inv0 = 1.f / l0r;
    const float inv1 = 1.f / l1r;
    #pragma unroll
    for (int nt = 0; nt < 4; nt++) {
        const int col = n * DH_ + wc * 32 + nt * 8 + 2 * t4;
        *(float2*)&av[(size_t)(b * Q_ + i0 + di0) * D_ + col] =
            make_float2(O[nt][0] * inv0, O[nt][1] * inv0);
        *(float2*)&av[(size_t)(b * Q_ + i0 + di1) * D_ + col] =
            make_float2(O[nt][2] * inv1, O[nt][3] * inv1);
    }
}

// ---------------- fused residual add + LayerNorm (shuffle reductions) ---------
__global__ void __launch_bounds__(256) add_ln_kernel(
    const float* __restrict__ x, const float* __restrict__ resid,
    const float* __restrict__ g, const float* __restrict__ bta,
    float* __restrict__ out)
{
    const int row = blockIdx.x;
    const int t = threadIdx.x;
    const int lane = t & 31;
    const int wid = t >> 5;
    __shared__ float red[8];
    __shared__ float bcast[2];

    float v[4];
    float s = 0.f;
    #pragma unroll
    for (int u = 0; u < 4; u++) {
        int c = t + u * 256;
        v[u] = x[(size_t)row * D_ + c] + resid[(size_t)row * D_ + c];
        s += v[u];
    }
    #pragma unroll
    for (int o = 16; o > 0; o >>= 1) s += __shfl_xor_sync(0xffffffffu, s, o);
    if (lane == 0) red[wid] = s;
    __syncthreads();
    if (t == 0) {
        float acc = 0.f;
        #pragma unroll
        for (int i = 0; i < 8; i++) acc += red[i];
        bcast[0] = acc * (1.f / D_);
    }
    __syncthreads();
    const float mean = bcast[0];

    s = 0.f;
    #pragma unroll
    for (int u = 0; u < 4; u++) {
        float dd = v[u] - mean;
        s += dd * dd;
    }
    #pragma unroll
    for (int o = 16; o > 0; o >>= 1) s += __shfl_xor_sync(0xffffffffu, s, o);
    if (lane == 0) red[wid] = s;
    __syncthreads();
    if (t == 0) {
        float acc = 0.f;
        #pragma unroll
        for (int i = 0; i < 8; i++) acc += red[i];
        bcast[1] = rsqrtf(acc * (1.f / D_) + 1e-5f);
    }
    __syncthreads();
    const float rstd = bcast[1];

    #pragma unroll
    for (int u = 0; u < 4; u++) {
        int c = t + u * 256;
        out[(size_t)row * D_ + c] = (v[u] - mean) * rstd * g[c] + bta[c];
    }
}

// ---------------- host launch -------------------------------------------------
extern "C" void kernel_launch(void* const* d_in, const int* in_sizes, int n_in,
                              void* d_out, int out_size)
{
    const float* w     = (const float*)d_in[0];
    const float* r     = (const float*)d_in[1];
    const float* qkv_w = (const float*)d_in[3];
    const float* r_w   = (const float*)d_in[4];
    const float* o_w   = (const float*)d_in[5];
    const float* rwb   = (const float*)d_in[6];
    const float* rrb   = (const float*)d_in[7];
    const float* ln1_g = (const float*)d_in[8];
    const float* ln1_b = (const float*)d_in[9];
    const float* ff_w1 = (const float*)d_in[10];
    const float* ff_b1 = (const float*)d_in[11];
    const float* ff_w2 = (const float*)d_in[12];
    const float* ff_b2 = (const float*)d_in[13];
    const float* ln2_g = (const float*)d_in[14];
    const float* ln2_b = (const float*)d_in[15];
    float* out = (float*)d_out;

    float *heads, *rk, *av, *tmp, *out1, *ff1;
    cudaGetSymbolAddress((void**)&heads, g_heads);
    cudaGetSymbolAddress((void**)&rk,    g_rk);
    cudaGetSymbolAddress((void**)&av,    g_av);
    cudaGetSymbolAddress((void**)&tmp,   g_tmp);
    cudaGetSymbolAddress((void**)&out1,  g_out1);
    cudaGetSymbolAddress((void**)&ff1,   g_ff1);

    cudaFuncSetAttribute(attn_mma,
        cudaFuncAttributeMaxDynamicSharedMemorySize, ATT_SMEM);
    cudaFuncSetAttribute(gemm_big<false, false>,
        cudaFuncAttributeMaxDynamicSharedMemorySize, GB_SMEM);
    cudaFuncSetAttribute(gemm_big<true, true>,
        cudaFuncAttributeMaxDynamicSharedMemorySize, GB_SMEM);
    cudaFuncSetAttribute(gemm_big<true, false>,
        cudaFuncAttributeMaxDynamicSharedMemorySize, GB_SMEM);

    // 1) QKV projection                                   [4096, 3072]
    gemm_big<false, false><<<dim3(D3 / 128, BQ / 256), 256, GB_SMEM>>>(
        w, qkv_w, nullptr, heads, BQ, D_, D3);

    // 2) rk = r @ r_w^T (small kernel for fill)           [1024, 1024]
    gemm_sm<<<dim3(D_ / 128, Q_ / 128), 256>>>(r, r_w, rk, D_, D_);

    // 3) MMA flash attention                              av [4096, 1024]
    attn_mma<<<dim3(Q_ / 64, N_, B_), 256, ATT_SMEM>>>(
        heads, rk, rwb, rrb, av);

    // 4) O projection                                     [4096, 1024]
    gemm_big<false, false><<<dim3(D_ / 128, BQ / 256), 256, GB_SMEM>>>(
        av, o_w, nullptr, tmp, BQ, D_, D_);

    // 5) out1 = LN(w + tmp)
    add_ln_kernel<<<BQ, 256>>>(tmp, w, ln1_g, ln1_b, out1);

    // 6) ff1 = relu(out1 @ ff_w1^T + b1)                  [4096, 4096]
    gemm_big<true, true><<<dim3(DI_ / 128, BQ / 256), 256, GB_SMEM>>>(
        out1, ff_w1, ff_b1, ff1, BQ, D_, DI_);

    // 7) tmp = ff1 @ ff_w2^T + b2                         [4096, 1024]
    gemm_big<true, false><<<dim3(D_ / 128, BQ / 256), 256, GB_SMEM>>>(
        ff1, ff_w2, ff_b2, tmp, BQ, DI_, D_);

    // 8) out = LN(out1 + tmp)
    add_ln_kernel<<<BQ, 256>>>(tmp, out1, ln2_g, ln2_b, out);
}

// round 13
// speedup vs baseline: 1.0639x; 1.0639x over previous
#include <cuda_runtime.h>
#include <cuda_bf16.h>
#include <math.h>
#include <stdint.h>

// Problem constants (fixed by the dataset)
#define B_  4
#define Q_  1024
#define D_  1024
#define N_  16
#define DH_ 64
#define DI_ 4096
#define BQ  (B_ * Q_)      // 4096
#define D3  (3 * D_)       // 3072

// ---------------- scratch (static device globals; no allocation) -------------
__device__ float g_heads[BQ * D3];   // 48 MB
__device__ float g_rk   [Q_ * D_];   //  4 MB
__device__ float g_av   [BQ * D_];   // 16 MB
__device__ float g_tmp  [BQ * D_];   // 16 MB
__device__ float g_out1 [BQ * D_];   // 16 MB
__device__ float g_ff1  [BQ * DI_];  // 64 MB

// ---------------- helpers ------------------------------------------------------
__device__ __forceinline__ uint32_t f2tf32(float x) {
    uint32_t r;
    asm("cvt.rna.tf32.f32 %0, %1;" : "=r"(r) : "f"(x));
    return r;
}
__device__ __forceinline__ void mma_tf32(float* d, const uint32_t* a,
                                         const uint32_t* b) {
    asm volatile(
        "mma.sync.aligned.m16n8k8.row.col.f32.tf32.tf32.f32 "
        "{%0,%1,%2,%3}, {%4,%5,%6,%7}, {%8,%9}, {%0,%1,%2,%3};"
        : "+f"(d[0]), "+f"(d[1]), "+f"(d[2]), "+f"(d[3])
        : "r"(a[0]), "r"(a[1]), "r"(a[2]), "r"(a[3]), "r"(b[0]), "r"(b[1]));
}

// ---- fragment-major smem addressing ----
__device__ __forceinline__ int a_word(int row, int k) {
    int ld = ((row & 7) << 2) | (k & 3);
    int e  = ((k & 4) >> 1) | ((row & 8) >> 3);
    int f  = ld ^ (ld >> 3);
    return (((k >> 3) << 3) | (row >> 4)) * 128 + f * 4 + e;
}
__device__ __forceinline__ int b_word(int row, int k) {
    int ld = ((row & 7) << 2) | (k & 3);
    int e  = (k & 4) >> 2;
    int h  = ld ^ (ld >> 3);
    return ((k >> 3) * 16 + (row >> 3)) * 72 + h * 2 + e;
}
// attention variants
__device__ __forceinline__ int bw8(int nn, int k) {
    int ld = ((nn & 7) << 2) | (k & 3);
    int e  = (k & 4) >> 2;
    int h  = ld ^ (ld >> 3);
    return ((k >> 3) * 8 + (nn >> 3)) * 72 + h * 2 + e;
}
__device__ __forceinline__ int aw4(int row, int k) {
    int ld = ((row & 7) << 2) | (k & 3);
    int e  = ((k & 4) >> 1) | ((row & 8) >> 3);
    int f  = ld ^ (ld >> 3);
    return ((k >> 3) * 4 + (row >> 4)) * 128 + f * 4 + e;
}

// ---------------- HMMA GEMM (R8 structure — measured best) --------------------
template<bool BIAS, bool RELU>
__global__ void __launch_bounds__(256, 2) gemm_mma(
    const float* __restrict__ A, const float* __restrict__ W,
    const float* __restrict__ bias, float* __restrict__ C,
    int M, int K, int ldc)
{
    constexpr int BK = 16;
    __shared__ uint32_t sAh[2][2048];
    __shared__ uint32_t sWh[2][2304];

    const int t    = threadIdx.x;
    const int m0   = blockIdx.y * 128;
    const int n0   = blockIdx.x * 128;
    const int lane = t & 31;
    const int w    = t >> 5;
    const int g    = lane >> 2;
    const int t4   = lane & 3;
    const int wm   = (w >> 1) * 32;
    const int wn   = (w & 1) * 64;
    const int mt0  = (w >> 1) * 2;
    const int nt0  = (w & 1) * 8;
    const int fl   = lane ^ (lane >> 3);
    const int lrow = t >> 1;
    const int lkq  = (t & 1) * 8;

    const float* Ap = A + (size_t)(m0 + lrow) * K + lkq;
    const float* Wp = W + (size_t)(n0 + lrow) * K + lkq;

    float acc[2][8][4];
    #pragma unroll
    for (int mt = 0; mt < 2; mt++)
        #pragma unroll
        for (int nt = 0; nt < 8; nt++)
            #pragma unroll
            for (int e = 0; e < 4; e++) acc[mt][nt][e] = 0.f;

    float4 pa0 = *(const float4*)Ap;
    float4 pa1 = *(const float4*)(Ap + 4);
    float4 pw0 = *(const float4*)Wp;
    float4 pw1 = *(const float4*)(Wp + 4);

    auto store_stage = [&](int bf_, float4 a0, float4 a1, float4 w0, float4 w1) {
        float va[8] = {a0.x, a0.y, a0.z, a0.w, a1.x, a1.y, a1.z, a1.w};
        float vw[8] = {w0.x, w0.y, w0.z, w0.w, w1.x, w1.y, w1.z, w1.w};
        #pragma unroll
        for (int u = 0; u < 8; u++) {
            const int k = lkq + u;
            sAh[bf_][a_word(lrow, k)] = f2tf32(va[u]);
            sWh[bf_][b_word(lrow, k)] = f2tf32(vw[u]);
        }
    };

    store_stage(0, pa0, pa1, pw0, pw1);
    __syncthreads();

    int buf = 0;
    for (int k0 = 0; k0 < K; k0 += BK) {
        const bool has_next = (k0 + BK < K);
        if (has_next) {
            pa0 = *(const float4*)(Ap + k0 + BK);
            pa1 = *(const float4*)(Ap + k0 + BK + 4);
            pw0 = *(const float4*)(Wp + k0 + BK);
            pw1 = *(const float4*)(Wp + k0 + BK + 4);
        }

        #pragma unroll
        for (int kk = 0; kk < 2; kk++) {
            uint4 af[2];
            uint2 bfr[8];
            #pragma unroll
            for (int mt = 0; mt < 2; mt++)
                af[mt] = *(const uint4*)&sAh[buf][(kk * 8 + mt0 + mt) * 128 + fl * 4];
            #pragma unroll
            for (int nt = 0; nt < 8; nt++)
                bfr[nt] = *(const uint2*)&sWh[buf][(kk * 16 + nt0 + nt) * 72 + fl * 2];
            #pragma unroll
            for (int mt = 0; mt < 2; mt++)
                #pragma unroll
                for (int nt = 0; nt < 8; nt++)
                    mma_tf32(acc[mt][nt], (const uint32_t*)&af[mt],
                             (const uint32_t*)&bfr[nt]);
        }

        if (has_next) {
            buf ^= 1;
            store_stage(buf, pa0, pa1, pw0, pw1);
            __syncthreads();
        }
    }

    #pragma unroll
    for (int mt = 0; mt < 2; mt++) {
        const int row = m0 + wm + mt * 16 + g;
        #pragma unroll
        for (int nt = 0; nt < 8; nt++) {
            const int col = n0 + wn + nt * 8 + 2 * t4;
            float b0v = BIAS ? bias[col]     : 0.f;
            float b1v = BIAS ? bias[col + 1] : 0.f;
            float x0 = acc[mt][nt][0] + b0v;
            float x1 = acc[mt][nt][1] + b1v;
            float x2 = acc[mt][nt][2] + b0v;
            float x3 = acc[mt][nt][3] + b1v;
            if (RELU) {
                x0 = fmaxf(x0, 0.f); x1 = fmaxf(x1, 0.f);
                x2 = fmaxf(x2, 0.f); x3 = fmaxf(x3, 0.f);
            }
            *(float2*)&C[(size_t)row * ldc + col]       = make_float2(x0, x1);
            *(float2*)&C[(size_t)(row + 8) * ldc + col] = make_float2(x2, x3);
        }
    }
}

// ---------------- MMA flash attention with rolling-band BD ---------------------
// BD values keyed by absolute rk row g = Q-1-i+j live in a 192-col smem ring
// (col = (g - (Q-64-i0)) mod 192). Tile j0 needs cols [j0, j0+126]; only the
// top 64 ([j0+63, j0+126]) are new -> one 64x64 BD MMA pass per tile (first
// tile computes 128). Gather: ring col = (j0 + 63 - di + dj) mod 192.
#define RSTR 197
#define ATT_WORDS (4608 + 4608 + 9216 + 64 * RSTR + 4096 + 256)
#define ATT_SMEM  (ATT_WORDS * 4)

__global__ void __launch_bounds__(256, 1) attn_mma(
    const float* __restrict__ heads, const float* __restrict__ rk,
    const float* __restrict__ rwb, const float* __restrict__ rrb,
    float* __restrict__ av)
{
    extern __shared__ uint32_t smw[];
    uint32_t* sK    = smw;                       // K: B-op (8 ntiles)
    uint32_t* sV    = sK + 4608;                 // V^T: B-op
    uint32_t* sBseg = sV + 4608;                 // rk segment(s): 2 x 4608
    float*    ring  = (float*)(sBseg + 9216);    // [64][RSTR] BD ring
    uint32_t* sP    = (uint32_t*)(ring + 64 * RSTR);  // P A-op (4096 w)
    float*    red   = (float*)(sP + 4096);       // reductions (256)

    const int i0   = (gridDim.x - 1 - blockIdx.x) * 64;  // heavy tiles first
    const int n    = blockIdx.y;
    const int b    = blockIdx.z;
    const int t    = threadIdx.x;
    const int lane = t & 31;
    const int w    = t >> 5;
    const int wr   = w & 3;
    const int wc   = w >> 2;
    const int g    = lane >> 2;
    const int t4   = lane & 3;
    const int fl   = lane ^ (lane >> 3);

    // ---- Q fragments in registers (tf32, biases folded) ----
    uint32_t qw[8][4], qr[8][4];
    {
        const float* qb = heads + (size_t)(b * Q_ + i0 + wr * 16 + g) * D3 + n * DH_;
        const float* wb_ = rwb + n * DH_;
        const float* rb_ = rrb + n * DH_;
        #pragma unroll
        for (int kt = 0; kt < 8; kt++) {
            const int c0 = kt * 8 + t4, c1 = c0 + 4;
            float q00 = qb[c0], q01 = qb[c1];
            float q10 = qb[8 * D3 + c0], q11 = qb[8 * D3 + c1];
            qw[kt][0] = f2tf32(q00 + wb_[c0]);
            qw[kt][1] = f2tf32(q10 + wb_[c0]);
            qw[kt][2] = f2tf32(q01 + wb_[c1]);
            qw[kt][3] = f2tf32(q11 + wb_[c1]);
            qr[kt][0] = f2tf32(q00 + rb_[c0]);
            qr[kt][1] = f2tf32(q10 + rb_[c0]);
            qr[kt][2] = f2tf32(q01 + rb_[c1]);
            qr[kt][3] = f2tf32(q11 + rb_[c1]);
        }
    }

    float O[4][4];
    #pragma unroll
    for (int nt = 0; nt < 4; nt++)
        #pragma unroll
        for (int e = 0; e < 4; e++) O[nt][e] = 0.f;
    float m0r = -1e30f, m1r = -1e30f, l0r = 0.f, l1r = 0.f;

    const int di0 = wr * 16 + g;
    const int di1 = di0 + 8;
    const int gbase0 = Q_ - 64 - i0;

    int rb0 = 63 - di0;          // (j0 + 63 - di) mod 192, j0 = 0
    int rb1 = 63 - di1;
    int wb  = 63;                // (j0 + 63) mod 192 (tile 0 special-cased)

    for (int j0 = 0; j0 <= i0; j0 += 64) {
        __syncthreads();   // prev PV / ring reads done

        // ---- stage K, V^T ----
        {
            const int jrow = t >> 2, d0 = (t & 3) * 16;
            const float* kp = heads + (size_t)(b * Q_ + j0 + jrow) * D3 + D_ + n * DH_ + d0;
            const float* vp = kp + D_;
            #pragma unroll
            for (int u = 0; u < 16; u += 4) {
                float4 kv = *(const float4*)(kp + u);
                float4 vv = *(const float4*)(vp + u);
                const int d = d0 + u;
                sK[bw8(jrow, d + 0)] = f2tf32(kv.x);
                sK[bw8(jrow, d + 1)] = f2tf32(kv.y);
                sK[bw8(jrow, d + 2)] = f2tf32(kv.z);
                sK[bw8(jrow, d + 3)] = f2tf32(kv.w);
                sV[bw8(d + 0, jrow)] = f2tf32(vv.x);
                sV[bw8(d + 1, jrow)] = f2tf32(vv.y);
                sV[bw8(d + 2, jrow)] = f2tf32(vv.z);
                sV[bw8(d + 3, jrow)] = f2tf32(vv.w);
            }
        }
        // ---- stage rk segment(s): first tile 128 rows, later tiles 64 ----
        if (j0 == 0) {
            const int s = t >> 1, d0 = (t & 1) * 32;
            int grow = gbase0 + s;
            if (grow > Q_ - 1) grow = Q_ - 1;
            const float* rp = rk + (size_t)grow * D_ + n * DH_ + d0;
            uint32_t* dst = sBseg + (s >> 6) * 4608;
            const int sr = s & 63;
            #pragma unroll
            for (int u = 0; u < 32; u += 4) {
                float4 rv = *(const float4*)(rp + u);
                const int d = d0 + u;
                dst[bw8(sr, d + 0)] = f2tf32(rv.x);
                dst[bw8(sr, d + 1)] = f2tf32(rv.y);
                dst[bw8(sr, d + 2)] = f2tf32(rv.z);
                dst[bw8(sr, d + 3)] = f2tf32(rv.w);
            }
        } else {
            const int s = t >> 2, d0 = (t & 3) * 16;
            int grow = gbase0 + j0 + 63 + s;
            if (grow > Q_ - 1) grow = Q_ - 1;
            const float* rp = rk + (size_t)grow * D_ + n * DH_ + d0;
            #pragma unroll
            for (int u = 0; u < 16; u += 4) {
                float4 rv = *(const float4*)(rp + u);
                const int d = d0 + u;
                sBseg[bw8(s, d + 0)] = f2tf32(rv.x);
                sBseg[bw8(s, d + 1)] = f2tf32(rv.y);
                sBseg[bw8(s, d + 2)] = f2tf32(rv.z);
                sBseg[bw8(s, d + 3)] = f2tf32(rv.w);
            }
        }
        __syncthreads();

        // ---- BD: new 64-col segment(s) = Qr @ rkseg^T -> ring ----
        {
            const int nseg = (j0 == 0) ? 2 : 1;
            for (int sg = 0; sg < nseg; sg++) {
                float bd[4][4];
                #pragma unroll
                for (int nt = 0; nt < 4; nt++)
                    #pragma unroll
                    for (int e = 0; e < 4; e++) bd[nt][e] = 0.f;
                #pragma unroll
                for (int kt = 0; kt < 8; kt++) {
                    uint2 bf[4];
                    #pragma unroll
                    for (int nt = 0; nt < 4; nt++)
                        bf[nt] = *(const uint2*)
                            &sBseg[sg * 4608 + (kt * 8 + wc * 4 + nt) * 72 + fl * 2];
                    #pragma unroll
                    for (int nt = 0; nt < 4; nt++)
                        mma_tf32(bd[nt], qr[kt], (const uint32_t*)&bf[nt]);
                }
                #pragma unroll
                for (int nt = 0; nt < 4; nt++) {
                    int c0;
                    if (j0 == 0) {
                        c0 = sg * 64 + wc * 32 + nt * 8 + 2 * t4;
                    } else {
                        c0 = wb + wc * 32 + nt * 8 + 2 * t4;
                        if (c0 >= 192) c0 -= 192;
                    }
                    int c1 = c0 + 1; if (c1 >= 192) c1 -= 192;
                    ring[di0 * RSTR + c0] = bd[nt][0];
                    ring[di0 * RSTR + c1] = bd[nt][1];
                    ring[di1 * RSTR + c0] = bd[nt][2];
                    ring[di1 * RSTR + c1] = bd[nt][3];
                }
            }
        }
        __syncthreads();

        // ---- S = AC + BD-gather, scale, causal mask ----
        float p[4][4];
        {
            float ac[4][4];
            #pragma unroll
            for (int nt = 0; nt < 4; nt++)
                #pragma unroll
                for (int e = 0; e < 4; e++) ac[nt][e] = 0.f;
            #pragma unroll
            for (int kt = 0; kt < 8; kt++) {
                uint2 kf[4];
                #pragma unroll
                for (int nt = 0; nt < 4; nt++)
                    kf[nt] = *(const uint2*)&sK[(kt * 8 + wc * 4 + nt) * 72 + fl * 2];
                #pragma unroll
                for (int nt = 0; nt < 4; nt++)
                    mma_tf32(ac[nt], qw[kt], (const uint32_t*)&kf[nt]);
            }
            const bool diag = (j0 == i0);
            #pragma unroll
            for (int nt = 0; nt < 4; nt++) {
                const int dj = wc * 32 + nt * 8 + 2 * t4;
                int x0 = rb0 + dj;     if (x0 >= 192) x0 -= 192;
                int x0b = x0 + 1;      if (x0b >= 192) x0b -= 192;
                int x1 = rb1 + dj;     if (x1 >= 192) x1 -= 192;
                int x1b = x1 + 1;      if (x1b >= 192) x1b -= 192;
                float v00 = (ac[nt][0] + ring[di0 * RSTR + x0])  * 0.125f;
                float v01 = (ac[nt][1] + ring[di0 * RSTR + x0b]) * 0.125f;
                float v10 = (ac[nt][2] + ring[di1 * RSTR + x1])  * 0.125f;
                float v11 = (ac[nt][3] + ring[di1 * RSTR + x1b]) * 0.125f;
                if (diag) {
                    if (dj     > di0) v00 = -1e30f;
                    if (dj + 1 > di0) v01 = -1e30f;
                    if (dj     > di1) v10 = -1e30f;
                    if (dj + 1 > di1) v11 = -1e30f;
                }
                p[nt][0] = v00; p[nt][1] = v01; p[nt][2] = v10; p[nt][3] = v11;
            }
        }

        // ---- online softmax ----
        {
            float mx0 = -1e30f, mx1 = -1e30f;
            #pragma unroll
            for (int nt = 0; nt < 4; nt++) {
                mx0 = fmaxf(mx0, fmaxf(p[nt][0], p[nt][1]));
                mx1 = fmaxf(mx1, fmaxf(p[nt][2], p[nt][3]));
            }
            mx0 = fmaxf(mx0, __shfl_xor_sync(0xffffffffu, mx0, 1));
            mx0 = fmaxf(mx0, __shfl_xor_sync(0xffffffffu, mx0, 2));
            mx1 = fmaxf(mx1, __shfl_xor_sync(0xffffffffu, mx1, 1));
            mx1 = fmaxf(mx1, __shfl_xor_sync(0xffffffffu, mx1, 2));
            if (t4 == 0) {
                red[wc * 64 + di0] = mx0;
                red[wc * 64 + di1] = mx1;
            }
        }
        __syncthreads();

        const float mn0 = fmaxf(m0r, fmaxf(red[di0], red[64 + di0]));
        const float mn1 = fmaxf(m1r, fmaxf(red[di1], red[64 + di1]));
        const float fac0 = __expf(m0r - mn0);
        const float fac1 = __expf(m1r - mn1);
        m0r = mn0; m1r = mn1;

        {
            float s0 = 0.f, s1 = 0.f;
            #pragma unroll
            for (int nt = 0; nt < 4; nt++) {
                p[nt][0] = __expf(p[nt][0] - mn0);
                p[nt][1] = __expf(p[nt][1] - mn0);
                p[nt][2] = __expf(p[nt][2] - mn1);
                p[nt][3] = __expf(p[nt][3] - mn1);
                s0 += p[nt][0] + p[nt][1];
                s1 += p[nt][2] + p[nt][3];
            }
            s0 += __shfl_xor_sync(0xffffffffu, s0, 1);
            s0 += __shfl_xor_sync(0xffffffffu, s0, 2);
            s1 += __shfl_xor_sync(0xffffffffu, s1, 1);
            s1 += __shfl_xor_sync(0xffffffffu, s1, 2);
            if (t4 == 0) {
                red[128 + wc * 64 + di0] = s0;
                red[128 + wc * 64 + di1] = s1;
            }
        }
        __syncthreads();

        l0r = l0r * fac0 + red[128 + di0] + red[128 + 64 + di0];
        l1r = l1r * fac1 + red[128 + di1] + red[128 + 64 + di1];
        #pragma unroll
        for (int nt = 0; nt < 4; nt++) {
            O[nt][0] *= fac0; O[nt][1] *= fac0;
            O[nt][2] *= fac1; O[nt][3] *= fac1;
        }

        // ---- P -> smem (tf32, A-fragment-major) ----
        #pragma unroll
        for (int nt = 0; nt < 4; nt++) {
            const int dj = wc * 32 + nt * 8 + 2 * t4;
            sP[aw4(di0, dj)]     = f2tf32(p[nt][0]);
            sP[aw4(di0, dj + 1)] = f2tf32(p[nt][1]);
            sP[aw4(di1, dj)]     = f2tf32(p[nt][2]);
            sP[aw4(di1, dj + 1)] = f2tf32(p[nt][3]);
        }
        __syncthreads();

        // ---- O += P @ V ----
        #pragma unroll
        for (int kt = 0; kt < 8; kt++) {
            uint4 af = *(const uint4*)&sP[(kt * 4 + wr) * 128 + fl * 4];
            uint2 vf[4];
            #pragma unroll
            for (int nt = 0; nt < 4; nt++)
                vf[nt] = *(const uint2*)&sV[(kt * 8 + wc * 4 + nt) * 72 + fl * 2];
            #pragma unroll
            for (int nt = 0; nt < 4; nt++)
                mma_tf32(O[nt], (const uint32_t*)&af, (const uint32_t*)&vf[nt]);
        }

        // ---- advance ring bases ----
        rb0 += 64; if (rb0 >= 192) rb0 -= 192;
        rb1 += 64; if (rb1 >= 192) rb1 -= 192;
        if (j0 == 0) wb = 127;
        else { wb += 64; if (wb >= 192) wb -= 192; }
    }

    const float inv0 = 1.f / l0r;
    const float inv1 = 1.f / l1r;
    #pragma unroll
    for (int nt = 0; nt < 4; nt++) {
        const int col = n * DH_ + wc * 32 + nt * 8 + 2 * t4;
        *(float2*)&av[(size_t)(b * Q_ + i0 + di0) * D_ + col] =
            make_float2(O[nt][0] * inv0, O[nt][1] * inv0);
        *(float2*)&av[(size_t)(b * Q_ + i0 + di1) * D_ + col] =
            make_float2(O[nt][2] * inv1, O[nt][3] * inv1);
    }
}

// ---------------- fused residual add + LayerNorm (shuffle reductions) ---------
__global__ void __launch_bounds__(256) add_ln_kernel(
    const float* __restrict__ x, const float* __restrict__ resid,
    const float* __restrict__ g, const float* __restrict__ bta,
    float* __restrict__ out)
{
    const int row = blockIdx.x;
    const int t = threadIdx.x;
    const int lane = t & 31;
    const int wid = t >> 5;
    __shared__ float red[8];
    __shared__ float bcast[2];

    float v[4];
    float s = 0.f;
    #pragma unroll
    for (int u = 0; u < 4; u++) {
        int c = t + u * 256;
        v[u] = x[(size_t)row * D_ + c] + resid[(size_t)row * D_ + c];
        s += v[u];
    }
    #pragma unroll
    for (int o = 16; o > 0; o >>= 1) s += __shfl_xor_sync(0xffffffffu, s, o);
    if (lane == 0) red[wid] = s;
    __syncthreads();
    if (t == 0) {
        float acc = 0.f;
        #pragma unroll
        for (int i = 0; i < 8; i++) acc += red[i];
        bcast[0] = acc * (1.f / D_);
    }
    __syncthreads();
    const float mean = bcast[0];

    s = 0.f;
    #pragma unroll
    for (int u = 0; u < 4; u++) {
        float dd = v[u] - mean;
        s += dd * dd;
    }
    #pragma unroll
    for (int o = 16; o > 0; o >>= 1) s += __shfl_xor_sync(0xffffffffu, s, o);
    if (lane == 0) red[wid] = s;
    __syncthreads();
    if (t == 0) {
        float acc = 0.f;
        #pragma unroll
        for (int i = 0; i < 8; i++) acc += red[i];
        bcast[1] = rsqrtf(acc * (1.f / D_) + 1e-5f);
    }
    __syncthreads();
    const float rstd = bcast[1];

    #pragma unroll
    for (int u = 0; u < 4; u++) {
        int c = t + u * 256;
        out[(size_t)row * D_ + c] = (v[u] - mean) * rstd * g[c] + bta[c];
    }
}

// ---------------- host launch -------------------------------------------------
extern "C" void kernel_launch(void* const* d_in, const int* in_sizes, int n_in,
                              void* d_out, int out_size)
{
    const float* w     = (const float*)d_in[0];
    const float* r     = (const float*)d_in[1];
    const float* qkv_w = (const float*)d_in[3];
    const float* r_w   = (const float*)d_in[4];
    const float* o_w   = (const float*)d_in[5];
    const float* rwb   = (const float*)d_in[6];
    const float* rrb   = (const float*)d_in[7];
    const float* ln1_g = (const float*)d_in[8];
    const float* ln1_b = (const float*)d_in[9];
    const float* ff_w1 = (const float*)d_in[10];
    const float* ff_b1 = (const float*)d_in[11];
    const float* ff_w2 = (const float*)d_in[12];
    const float* ff_b2 = (const float*)d_in[13];
    const float* ln2_g = (const float*)d_in[14];
    const float* ln2_b = (const float*)d_in[15];
    float* out = (float*)d_out;

    float *heads, *rk, *av, *tmp, *out1, *ff1;
    cudaGetSymbolAddress((void**)&heads, g_heads);
    cudaGetSymbolAddress((void**)&rk,    g_rk);
    cudaGetSymbolAddress((void**)&av,    g_av);
    cudaGetSymbolAddress((void**)&tmp,   g_tmp);
    cudaGetSymbolAddress((void**)&out1,  g_out1);
    cudaGetSymbolAddress((void**)&ff1,   g_ff1);

    cudaFuncSetAttribute(attn_mma,
        cudaFuncAttributeMaxDynamicSharedMemorySize, ATT_SMEM);

    // 1) QKV projection                                   [4096, 3072]
    gemm_mma<false, false><<<dim3(D3 / 128, BQ / 128), 256>>>(
        w, qkv_w, nullptr, heads, BQ, D_, D3);

    // 2) rk = r @ r_w^T                                   [1024, 1024]
    gemm_mma<false, false><<<dim3(D_ / 128, Q_ / 128), 256>>>(
        r, r_w, nullptr, rk, Q_, D_, D_);

    // 3) MMA flash attention (rolling-band BD)            av [4096, 1024]
    attn_mma<<<dim3(Q_ / 64, N_, B_), 256, ATT_SMEM>>>(
        heads, rk, rwb, rrb, av);

    // 4) O projection                                     [4096, 1024]
    gemm_mma<false, false><<<dim3(D_ / 128, BQ / 128), 256>>>(
        av, o_w, nullptr, tmp, BQ, D_, D_);

    // 5) out1 = LN(w + tmp)
    add_ln_kernel<<<BQ, 256>>>(tmp, w, ln1_g, ln1_b, out1);

    // 6) ff1 = relu(out1 @ ff_w1^T + b1)                  [4096, 4096]
    gemm_mma<true, true><<<dim3(DI_ / 128, BQ / 128), 256>>>(
        out1, ff_w1, ff_b1, ff1, BQ, D_, DI_);

    // 7) tmp = ff1 @ ff_w2^T + b2                         [4096, 1024]
    gemm_mma<true, false><<<dim3(D_ / 128, BQ / 128), 256>>>(
        ff1, ff_w2, ff_b2, tmp, BQ, DI_, D_);

    // 8) out = LN(out1 + tmp)
    add_ln_kernel<<<BQ, 256>>>(tmp, out1, ln2_g, ln2_b, out);
}

// round 14
// speedup vs baseline: 1.5718x; 1.4773x over previous
#include <cuda_runtime.h>
#include <cuda_bf16.h>
#include <math.h>
#include <stdint.h>

// Problem constants (fixed by the dataset)
#define B_  4
#define Q_  1024
#define D_  1024
#define N_  16
#define DH_ 64
#define DI_ 4096
#define BQ  (B_ * Q_)      // 4096
#define D3  (3 * D_)       // 3072

// ---------------- scratch (static device globals; no allocation) -------------
__device__ float g_heads[BQ * D3];   // 48 MB
__device__ float g_rk   [Q_ * D_];   //  4 MB
__device__ float g_av   [BQ * D_];   // 16 MB
__device__ float g_tmp  [BQ * D_];   // 16 MB
__device__ float g_out1 [BQ * D_];   // 16 MB
__device__ float g_ff1  [BQ * DI_];  // 64 MB

// ---------------- helpers ------------------------------------------------------
// pack two fp32 into one f16x2 register: lo = first arg, hi = second arg
__device__ __forceinline__ uint32_t pk2h(float lo, float hi) {
    uint32_t r;
    asm("cvt.rn.f16x2.f32 %0, %2, %1;" : "=r"(r) : "f"(lo), "f"(hi));
    return r;
}
// m16n8k16 fp16 MMA, fp32 accumulate
__device__ __forceinline__ void mma_f16(float* d, const uint32_t* a,
                                        const uint32_t* b) {
    asm volatile(
        "mma.sync.aligned.m16n8k16.row.col.f32.f16.f16.f32 "
        "{%0,%1,%2,%3}, {%4,%5,%6,%7}, {%8,%9}, {%0,%1,%2,%3};"
        : "+f"(d[0]), "+f"(d[1]), "+f"(d[2]), "+f"(d[3])
        : "r"(a[0]), "r"(a[1]), "r"(a[2]), "r"(a[3]), "r"(b[0]), "r"(b[1]));
}

// ---- fp16 fragment-major smem addressing (kp = k-pair index) ----
// A tile: 16 rows x 16 k = 128 words. word = f*4 + e; LDS.128 conflict-free.
__device__ __forceinline__ int ah_inner(int row, int kp) {
    int ld = ((row & 7) << 2) | (kp & 3);
    int e  = ((kp & 4) >> 1) | ((row & 8) >> 3);
    int f  = ld ^ (ld >> 3);
    return f * 4 + e;
}
// GEMM A (one ktile16 per chunk, 8 mtiles): kp 0..7
__device__ __forceinline__ int ah_word(int row, int kp) {
    return (row >> 4) * 128 + ah_inner(row, kp);
}
// GEMM B (one ktile16 per chunk, 16 ntiles, stride 72): kp 0..7
__device__ __forceinline__ int bh_word(int row, int kp) {
    int ld = ((row & 7) << 2) | (kp & 3);
    int e  = (kp & 4) >> 2;
    int h  = ld ^ (ld >> 3);
    return (row >> 3) * 72 + h * 2 + e;
}
// attention B-op: 8 ntiles per ktile, kp global 0..31
__device__ __forceinline__ int bw8h(int nn, int kp) {
    int ld = ((nn & 7) << 2) | (kp & 3);
    int e  = (kp & 4) >> 2;
    int h  = ld ^ (ld >> 3);
    return ((kp >> 3) * 8 + (nn >> 3)) * 72 + h * 2 + e;
}
// attention A-op (P): 4 mtiles per ktile, kp global 0..31
__device__ __forceinline__ int aw4h(int row, int kp) {
    return ((kp >> 3) * 4 + (row >> 4)) * 128 + ah_inner(row, kp & 7);
}

// ---------------- fp16 HMMA GEMM: C = A[M,K] @ W[N,K]^T (+bias)(+relu) --------
// 128x128 tile, BK=16 (one k16 step), 256 threads (8 warps 4x2), wtile 32x64.
template<bool BIAS, bool RELU>
__global__ void __launch_bounds__(256, 2) gemm_mma(
    const float* __restrict__ A, const float* __restrict__ W,
    const float* __restrict__ bias, float* __restrict__ C,
    int M, int K, int ldc)
{
    __shared__ uint32_t sAh[2][1024];
    __shared__ uint32_t sWh[2][1152];

    const int t    = threadIdx.x;
    const int m0   = blockIdx.y * 128;
    const int n0   = blockIdx.x * 128;
    const int lane = t & 31;
    const int w    = t >> 5;
    const int g    = lane >> 2;
    const int t4   = lane & 3;
    const int wm   = (w >> 1) * 32;
    const int wn   = (w & 1) * 64;
    const int mt0  = (w >> 1) * 2;
    const int nt0  = (w & 1) * 8;
    const int fl   = lane ^ (lane >> 3);
    const int lrow = t >> 1;
    const int lkq  = (t & 1) * 8;       // k offset (0 or 8) -> kp base 0 or 4

    const float* Ap = A + (size_t)(m0 + lrow) * K + lkq;
    const float* Wp = W + (size_t)(n0 + lrow) * K + lkq;

    float acc[2][8][4];
    #pragma unroll
    for (int mt = 0; mt < 2; mt++)
        #pragma unroll
        for (int nt = 0; nt < 8; nt++)
            #pragma unroll
            for (int e = 0; e < 4; e++) acc[mt][nt][e] = 0.f;

    float4 pa0 = *(const float4*)Ap;
    float4 pa1 = *(const float4*)(Ap + 4);
    float4 pw0 = *(const float4*)Wp;
    float4 pw1 = *(const float4*)(Wp + 4);

    auto store_stage = [&](int bf_, float4 a0, float4 a1, float4 w0, float4 w1) {
        float va[8] = {a0.x, a0.y, a0.z, a0.w, a1.x, a1.y, a1.z, a1.w};
        float vw[8] = {w0.x, w0.y, w0.z, w0.w, w1.x, w1.y, w1.z, w1.w};
        const int kpb = lkq >> 1;     // 0 or 4
        #pragma unroll
        for (int u = 0; u < 4; u++) {
            sAh[bf_][ah_word(lrow, kpb + u)] = pk2h(va[2 * u], va[2 * u + 1]);
            sWh[bf_][bh_word(lrow, kpb + u)] = pk2h(vw[2 * u], vw[2 * u + 1]);
        }
    };

    store_stage(0, pa0, pa1, pw0, pw1);
    __syncthreads();

    int buf = 0;
    for (int k0 = 0; k0 < K; k0 += 16) {
        const bool has_next = (k0 + 16 < K);
        if (has_next) {
            pa0 = *(const float4*)(Ap + k0 + 16);
            pa1 = *(const float4*)(Ap + k0 + 20);
            pw0 = *(const float4*)(Wp + k0 + 16);
            pw1 = *(const float4*)(Wp + k0 + 20);
        }

        {
            uint4 af[2];
            uint2 bfr[8];
            #pragma unroll
            for (int mt = 0; mt < 2; mt++)
                af[mt] = *(const uint4*)&sAh[buf][(mt0 + mt) * 128 + fl * 4];
            #pragma unroll
            for (int nt = 0; nt < 8; nt++)
                bfr[nt] = *(const uint2*)&sWh[buf][(nt0 + nt) * 72 + fl * 2];
            #pragma unroll
            for (int mt = 0; mt < 2; mt++)
                #pragma unroll
                for (int nt = 0; nt < 8; nt++)
                    mma_f16(acc[mt][nt], (const uint32_t*)&af[mt],
                            (const uint32_t*)&bfr[nt]);
        }

        if (has_next) {
            buf ^= 1;
            store_stage(buf, pa0, pa1, pw0, pw1);
            __syncthreads();
        }
    }

    #pragma unroll
    for (int mt = 0; mt < 2; mt++) {
        const int row = m0 + wm + mt * 16 + g;
        #pragma unroll
        for (int nt = 0; nt < 8; nt++) {
            const int col = n0 + wn + nt * 8 + 2 * t4;
            float b0v = BIAS ? bias[col]     : 0.f;
            float b1v = BIAS ? bias[col + 1] : 0.f;
            float x0 = acc[mt][nt][0] + b0v;
            float x1 = acc[mt][nt][1] + b1v;
            float x2 = acc[mt][nt][2] + b0v;
            float x3 = acc[mt][nt][3] + b1v;
            if (RELU) {
                x0 = fmaxf(x0, 0.f); x1 = fmaxf(x1, 0.f);
                x2 = fmaxf(x2, 0.f); x3 = fmaxf(x3, 0.f);
            }
            *(float2*)&C[(size_t)row * ldc + col]       = make_float2(x0, x1);
            *(float2*)&C[(size_t)(row + 8) * ldc + col] = make_float2(x2, x3);
        }
    }
}

// ---------------- fp16 MMA flash attention with rolling-band BD ----------------
// Smem (words): sK 2304 | sV 2304 | sBseg 4608 | ring 64*197 fp32 | sP 2048 | red 256
#define RSTR 197
#define ATT_WORDS (2304 + 2304 + 4608 + 64 * RSTR + 2048 + 256)
#define ATT_SMEM  (ATT_WORDS * 4)

__global__ void __launch_bounds__(256, 1) attn_mma(
    const float* __restrict__ heads, const float* __restrict__ rk,
    const float* __restrict__ rwb, const float* __restrict__ rrb,
    float* __restrict__ av)
{
    extern __shared__ uint32_t smw[];
    uint32_t* sK    = smw;                       // K: B-op (n=j, k=d)
    uint32_t* sV    = sK + 2304;                 // V^T: B-op (n=d, k=j)
    uint32_t* sBseg = sV + 2304;                 // rk segs: 2 x 2304
    float*    ring  = (float*)(sBseg + 4608);    // [64][RSTR] BD ring (fp32)
    uint32_t* sP    = (uint32_t*)(ring + 64 * RSTR);  // P A-op (2048 w)
    float*    red   = (float*)(sP + 2048);       // reductions (256)

    const int i0   = (gridDim.x - 1 - blockIdx.x) * 64;  // heavy tiles first
    const int n    = blockIdx.y;
    const int b    = blockIdx.z;
    const int t    = threadIdx.x;
    const int lane = t & 31;
    const int w    = t >> 5;
    const int wr   = w & 3;
    const int wc   = w >> 2;
    const int g    = lane >> 2;
    const int t4   = lane & 3;
    const int fl   = lane ^ (lane >> 3);

    const int di0 = wr * 16 + g;
    const int di1 = di0 + 8;

    // ---- Q fragments (fp16, biases folded): 4 k16-steps ----
    uint32_t qw[4][4], qr[4][4];
    {
        const float* qb = heads + (size_t)(b * Q_ + i0 + di0) * D3 + n * DH_;
        const float* wb_ = rwb + n * DH_;
        const float* rb_ = rrb + n * DH_;
        #pragma unroll
        for (int kt = 0; kt < 4; kt++) {
            const int cl = kt * 16 + 2 * t4;
            const int ch = cl + 8;
            float2 ql0 = *(const float2*)(qb + cl);
            float2 qh0 = *(const float2*)(qb + ch);
            float2 ql1 = *(const float2*)(qb + 8 * D3 + cl);
            float2 qh1 = *(const float2*)(qb + 8 * D3 + ch);
            float2 wl = *(const float2*)(wb_ + cl);
            float2 wh = *(const float2*)(wb_ + ch);
            float2 rl = *(const float2*)(rb_ + cl);
            float2 rh = *(const float2*)(rb_ + ch);
            qw[kt][0] = pk2h(ql0.x + wl.x, ql0.y + wl.y);
            qw[kt][1] = pk2h(ql1.x + wl.x, ql1.y + wl.y);
            qw[kt][2] = pk2h(qh0.x + wh.x, qh0.y + wh.y);
            qw[kt][3] = pk2h(qh1.x + wh.x, qh1.y + wh.y);
            qr[kt][0] = pk2h(ql0.x + rl.x, ql0.y + rl.y);
            qr[kt][1] = pk2h(ql1.x + rl.x, ql1.y + rl.y);
            qr[kt][2] = pk2h(qh0.x + rh.x, qh0.y + rh.y);
            qr[kt][3] = pk2h(qh1.x + rh.x, qh1.y + rh.y);
        }
    }

    float O[4][4];
    #pragma unroll
    for (int nt = 0; nt < 4; nt++)
        #pragma unroll
        for (int e = 0; e < 4; e++) O[nt][e] = 0.f;
    float m0r = -1e30f, m1r = -1e30f, l0r = 0.f, l1r = 0.f;

    const int gbase0 = Q_ - 64 - i0;
    int rb0 = 63 - di0;          // ring col of dj=0 for row di0
    int rb1 = 63 - di1;
    int wb  = 63;                // ring write base (tile 0 special-cased)

    for (int j0 = 0; j0 <= i0; j0 += 64) {
        __syncthreads();   // prev PV / ring reads done

        // ---- stage K (fp16 pairs along d) ----
        {
            const int jrow = t >> 2, d0 = (t & 3) * 16;
            const float* kp_ = heads + (size_t)(b * Q_ + j0 + jrow) * D3 + D_ + n * DH_ + d0;
            #pragma unroll
            for (int u = 0; u < 16; u += 4) {
                float4 kv = *(const float4*)(kp_ + u);
                const int kp = (d0 + u) >> 1;
                sK[bw8h(jrow, kp)]     = pk2h(kv.x, kv.y);
                sK[bw8h(jrow, kp + 1)] = pk2h(kv.z, kv.w);
            }
        }
        // ---- stage V^T (fp16 pairs along j) ----
        {
            const int jp = t >> 3;          // j pair 0..31
            const int d0 = (t & 7) * 8;
            const float* v0 = heads + (size_t)(b * Q_ + j0 + 2 * jp) * D3 + 2 * D_ + n * DH_ + d0;
            const float* v1 = v0 + D3;
            float4 x0 = *(const float4*)v0;
            float4 x1 = *(const float4*)(v0 + 4);
            float4 y0 = *(const float4*)v1;
            float4 y1 = *(const float4*)(v1 + 4);
            float va[8] = {x0.x, x0.y, x0.z, x0.w, x1.x, x1.y, x1.z, x1.w};
            float vb[8] = {y0.x, y0.y, y0.z, y0.w, y1.x, y1.y, y1.z, y1.w};
            #pragma unroll
            for (int u = 0; u < 8; u++)
                sV[bw8h(d0 + u, jp)] = pk2h(va[u], vb[u]);
        }
        // ---- stage rk segment(s) ----
        if (j0 == 0) {
            const int s = t >> 1, d0 = (t & 1) * 32;
            int grow = gbase0 + s;
            if (grow > Q_ - 1) grow = Q_ - 1;
            const float* rp = rk + (size_t)grow * D_ + n * DH_ + d0;
            uint32_t* dst = sBseg + (s >> 6) * 2304;
            const int sr = s & 63;
            #pragma unroll
            for (int u = 0; u < 32; u += 4) {
                float4 rv = *(const float4*)(rp + u);
                const int kp = (d0 + u) >> 1;
                dst[bw8h(sr, kp)]     = pk2h(rv.x, rv.y);
                dst[bw8h(sr, kp + 1)] = pk2h(rv.z, rv.w);
            }
        } else {
            const int s = t >> 2, d0 = (t & 3) * 16;
            int grow = gbase0 + j0 + 63 + s;
            if (grow > Q_ - 1) grow = Q_ - 1;
            const float* rp = rk + (size_t)grow * D_ + n * DH_ + d0;
            #pragma unroll
            for (int u = 0; u < 16; u += 4) {
                float4 rv = *(const float4*)(rp + u);
                const int kp = (d0 + u) >> 1;
                sBseg[bw8h(s, kp)]     = pk2h(rv.x, rv.y);
                sBseg[bw8h(s, kp + 1)] = pk2h(rv.z, rv.w);
            }
        }
        __syncthreads();

        // ---- BD: new 64-col segment(s) = Qr @ rkseg^T -> ring ----
        {
            const int nseg = (j0 == 0) ? 2 : 1;
            for (int sg = 0; sg < nseg; sg++) {
                float bd[4][4];
                #pragma unroll
                for (int nt = 0; nt < 4; nt++)
                    #pragma unroll
                    for (int e = 0; e < 4; e++) bd[nt][e] = 0.f;
                #pragma unroll
                for (int kt = 0; kt < 4; kt++) {
                    uint2 bf[4];
                    #pragma unroll
                    for (int nt = 0; nt < 4; nt++)
                        bf[nt] = *(const uint2*)
                            &sBseg[sg * 2304 + (kt * 8 + wc * 4 + nt) * 72 + fl * 2];
                    #pragma unroll
                    for (int nt = 0; nt < 4; nt++)
                        mma_f16(bd[nt], qr[kt], (const uint32_t*)&bf[nt]);
                }
                #pragma unroll
                for (int nt = 0; nt < 4; nt++) {
                    int c0;
                    if (j0 == 0) {
                        c0 = sg * 64 + wc * 32 + nt * 8 + 2 * t4;
                    } else {
                        c0 = wb + wc * 32 + nt * 8 + 2 * t4;
                        if (c0 >= 192) c0 -= 192;
                    }
                    int c1 = c0 + 1; if (c1 >= 192) c1 -= 192;
                    ring[di0 * RSTR + c0] = bd[nt][0];
                    ring[di0 * RSTR + c1] = bd[nt][1];
                    ring[di1 * RSTR + c0] = bd[nt][2];
                    ring[di1 * RSTR + c1] = bd[nt][3];
                }
            }
        }
        __syncthreads();

        // ---- S = AC + BD-gather, scale, causal mask ----
        float p[4][4];
        {
            float ac[4][4];
            #pragma unroll
            for (int nt = 0; nt < 4; nt++)
                #pragma unroll
                for (int e = 0; e < 4; e++) ac[nt][e] = 0.f;
            #pragma unroll
            for (int kt = 0; kt < 4; kt++) {
                uint2 kf[4];
                #pragma unroll
                for (int nt = 0; nt < 4; nt++)
                    kf[nt] = *(const uint2*)&sK[(kt * 8 + wc * 4 + nt) * 72 + fl * 2];
                #pragma unroll
                for (int nt = 0; nt < 4; nt++)
                    mma_f16(ac[nt], qw[kt], (const uint32_t*)&kf[nt]);
            }
            const bool diag = (j0 == i0);
            #pragma unroll
            for (int nt = 0; nt < 4; nt++) {
                const int dj = wc * 32 + nt * 8 + 2 * t4;
                int x0 = rb0 + dj;     if (x0 >= 192) x0 -= 192;
                int x0b = x0 + 1;      if (x0b >= 192) x0b -= 192;
                int x1 = rb1 + dj;     if (x1 >= 192) x1 -= 192;
                int x1b = x1 + 1;      if (x1b >= 192) x1b -= 192;
                float v00 = (ac[nt][0] + ring[di0 * RSTR + x0])  * 0.125f;
                float v01 = (ac[nt][1] + ring[di0 * RSTR + x0b]) * 0.125f;
                float v10 = (ac[nt][2] + ring[di1 * RSTR + x1])  * 0.125f;
                float v11 = (ac[nt][3] + ring[di1 * RSTR + x1b]) * 0.125f;
                if (diag) {
                    if (dj     > di0) v00 = -1e30f;
                    if (dj + 1 > di0) v01 = -1e30f;
                    if (dj     > di1) v10 = -1e30f;
                    if (dj + 1 > di1) v11 = -1e30f;
                }
                p[nt][0] = v00; p[nt][1] = v01; p[nt][2] = v10; p[nt][3] = v11;
            }
        }

        // ---- online softmax ----
        {
            float mx0 = -1e30f, mx1 = -1e30f;
            #pragma unroll
            for (int nt = 0; nt < 4; nt++) {
                mx0 = fmaxf(mx0, fmaxf(p[nt][0], p[nt][1]));
                mx1 = fmaxf(mx1, fmaxf(p[nt][2], p[nt][3]));
            }
            mx0 = fmaxf(mx0, __shfl_xor_sync(0xffffffffu, mx0, 1));
            mx0 = fmaxf(mx0, __shfl_xor_sync(0xffffffffu, mx0, 2));
            mx1 = fmaxf(mx1, __shfl_xor_sync(0xffffffffu, mx1, 1));
            mx1 = fmaxf(mx1, __shfl_xor_sync(0xffffffffu, mx1, 2));
            if (t4 == 0) {
                red[wc * 64 + di0] = mx0;
                red[wc * 64 + di1] = mx1;
            }
        }
        __syncthreads();

        const float mn0 = fmaxf(m0r, fmaxf(red[di0], red[64 + di0]));
        const float mn1 = fmaxf(m1r, fmaxf(red[di1], red[64 + di1]));
        const float fac0 = __expf(m0r - mn0);
        const float fac1 = __expf(m1r - mn1);
        m0r = mn0; m1r = mn1;

        {
            float s0 = 0.f, s1 = 0.f;
            #pragma unroll
            for (int nt = 0; nt < 4; nt++) {
                p[nt][0] = __expf(p[nt][0] - mn0);
                p[nt][1] = __expf(p[nt][1] - mn0);
                p[nt][2] = __expf(p[nt][2] - mn1);
                p[nt][3] = __expf(p[nt][3] - mn1);
                s0 += p[nt][0] + p[nt][1];
                s1 += p[nt][2] + p[nt][3];
            }
            s0 += __shfl_xor_sync(0xffffffffu, s0, 1);
            s0 += __shfl_xor_sync(0xffffffffu, s0, 2);
            s1 += __shfl_xor_sync(0xffffffffu, s1, 1);
            s1 += __shfl_xor_sync(0xffffffffu, s1, 2);
            if (t4 == 0) {
                red[128 + wc * 64 + di0] = s0;
                red[128 + wc * 64 + di1] = s1;
            }
        }
        __syncthreads();

        l0r = l0r * fac0 + red[128 + di0] + red[128 + 64 + di0];
        l1r = l1r * fac1 + red[128 + di1] + red[128 + 64 + di1];
        #pragma unroll
        for (int nt = 0; nt < 4; nt++) {
            O[nt][0] *= fac0; O[nt][1] *= fac0;
            O[nt][2] *= fac1; O[nt][3] *= fac1;
        }

        // ---- P -> smem (fp16 pairs, A-fragment-major) ----
        #pragma unroll
        for (int nt = 0; nt < 4; nt++) {
            const int dj = wc * 32 + nt * 8 + 2 * t4;
            const int kp = dj >> 1;
            sP[aw4h(di0, kp)] = pk2h(p[nt][0], p[nt][1]);
            sP[aw4h(di1, kp)] = pk2h(p[nt][2], p[nt][3]);
        }
        __syncthreads();

        // ---- O += P @ V ----
        #pragma unroll
        for (int kt = 0; kt < 4; kt++) {
            uint4 af = *(const uint4*)&sP[(kt * 4 + wr) * 128 + fl * 4];
            uint2 vf[4];
            #pragma unroll
            for (int nt = 0; nt < 4; nt++)
                vf[nt] = *(const uint2*)&sV[(kt * 8 + wc * 4 + nt) * 72 + fl * 2];
            #pragma unroll
            for (int nt = 0; nt < 4; nt++)
                mma_f16(O[nt], (const uint32_t*)&af, (const uint32_t*)&vf[nt]);
        }

        // ---- advance ring bases ----
        rb0 += 64; if (rb0 >= 192) rb0 -= 192;
        rb1 += 64; if (rb1 >= 192) rb1 -= 192;
        if (j0 == 0) wb = 127;
        else { wb += 64; if (wb >= 192) wb -= 192; }
    }

    const float inv0 = 1.f / l0r;
    const float inv1 = 1.f / l1r;
    #pragma unroll
    for (int nt = 0; nt < 4; nt++) {
        const int col = n * DH_ + wc * 32 + nt * 8 + 2 * t4;
        *(float2*)&av[(size_t)(b * Q_ + i0 + di0) * D_ + col] =
            make_float2(O[nt][0] * inv0, O[nt][1] * inv0);
        *(float2*)&av[(size_t)(b * Q_ + i0 + di1) * D_ + col] =
            make_float2(O[nt][2] * inv1, O[nt][3] * inv1);
    }
}

// ---------------- fused residual add + LayerNorm (shuffle reductions) ---------
__global__ void __launch_bounds__(256) add_ln_kernel(
    const float* __restrict__ x, const float* __restrict__ resid,
    const float* __restrict__ g, const float* __restrict__ bta,
    float* __restrict__ out)
{
    const int row = blockIdx.x;
    const int t = threadIdx.x;
    const int lane = t & 31;
    const int wid = t >> 5;
    __shared__ float red[8];
    __shared__ float bcast[2];

    float v[4];
    float s = 0.f;
    #pragma unroll
    for (int u = 0; u < 4; u++) {
        int c = t + u * 256;
        v[u] = x[(size_t)row * D_ + c] + resid[(size_t)row * D_ + c];
        s += v[u];
    }
    #pragma unroll
    for (int o = 16; o > 0; o >>= 1) s += __shfl_xor_sync(0xffffffffu, s, o);
    if (lane == 0) red[wid] = s;
    __syncthreads();
    if (t == 0) {
        float acc = 0.f;
        #pragma unroll
        for (int i = 0; i < 8; i++) acc += red[i];
        bcast[0] = acc * (1.f / D_);
    }
    __syncthreads();
    const float mean = bcast[0];

    s = 0.f;
    #pragma unroll
    for (int u = 0; u < 4; u++) {
        float dd = v[u] - mean;
        s += dd * dd;
    }
    #pragma unroll
    for (int o = 16; o > 0; o >>= 1) s += __shfl_xor_sync(0xffffffffu, s, o);
    if (lane == 0) red[wid] = s;
    __syncthreads();
    if (t == 0) {
        float acc = 0.f;
        #pragma unroll
        for (int i = 0; i < 8; i++) acc += red[i];
        bcast[1] = rsqrtf(acc * (1.f / D_) + 1e-5f);
    }
    __syncthreads();
    const float rstd = bcast[1];

    #pragma unroll
    for (int u = 0; u < 4; u++) {
        int c = t + u * 256;
        out[(size_t)row * D_ + c] = (v[u] - mean) * rstd * g[c] + bta[c];
    }
}

// ---------------- host launch -------------------------------------------------
extern "C" void kernel_launch(void* const* d_in, const int* in_sizes, int n_in,
                              void* d_out, int out_size)
{
    const float* w     = (const float*)d_in[0];
    const float* r     = (const float*)d_in[1];
    const float* qkv_w = (const float*)d_in[3];
    const float* r_w   = (const float*)d_in[4];
    const float* o_w   = (const float*)d_in[5];
    const float* rwb   = (const float*)d_in[6];
    const float* rrb   = (const float*)d_in[7];
    const float* ln1_g = (const float*)d_in[8];
    const float* ln1_b = (const float*)d_in[9];
    const float* ff_w1 = (const float*)d_in[10];
    const float* ff_b1 = (const float*)d_in[11];
    const float* ff_w2 = (const float*)d_in[12];
    const float* ff_b2 = (const float*)d_in[13];
    const float* ln2_g = (const float*)d_in[14];
    const float* ln2_b = (const float*)d_in[15];
    float* out = (float*)d_out;

    float *heads, *rk, *av, *tmp, *out1, *ff1;
    cudaGetSymbolAddress((void**)&heads, g_heads);
    cudaGetSymbolAddress((void**)&rk,    g_rk);
    cudaGetSymbolAddress((void**)&av,    g_av);
    cudaGetSymbolAddress((void**)&tmp,   g_tmp);
    cudaGetSymbolAddress((void**)&out1,  g_out1);
    cudaGetSymbolAddress((void**)&ff1,   g_ff1);

    cudaFuncSetAttribute(attn_mma,
        cudaFuncAttributeMaxDynamicSharedMemorySize, ATT_SMEM);

    // 1) QKV projection                                   [4096, 3072]
    gemm_mma<false, false><<<dim3(D3 / 128, BQ / 128), 256>>>(
        w, qkv_w, nullptr, heads, BQ, D_, D3);

    // 2) rk = r @ r_w^T                                   [1024, 1024]
    gemm_mma<false, false><<<dim3(D_ / 128, Q_ / 128), 256>>>(
        r, r_w, nullptr, rk, Q_, D_, D_);

    // 3) fp16 MMA flash attention (rolling-band BD)       av [4096, 1024]
    attn_mma<<<dim3(Q_ / 64, N_, B_), 256, ATT_SMEM>>>(
        heads, rk, rwb, rrb, av);

    // 4) O projection                                     [4096, 1024]
    gemm_mma<false, false><<<dim3(D_ / 128, BQ / 128), 256>>>(
        av, o_w, nullptr, tmp, BQ, D_, D_);

    // 5) out1 = LN(w + tmp)
    add_ln_kernel<<<BQ, 256>>>(tmp, w, ln1_g, ln1_b, out1);

    // 6) ff1 = relu(out1 @ ff_w1^T + b1)                  [4096, 4096]
    gemm_mma<true, true><<<dim3(DI_ / 128, BQ / 128), 256>>>(
        out1, ff_w1, ff_b1, ff1, BQ, D_, DI_);

    // 7) tmp = ff1 @ ff_w2^T + b2                         [4096, 1024]
    gemm_mma<true, false><<<dim3(D_ / 128, BQ / 128), 256>>>(
        ff1, ff_w2, ff_b2, tmp, BQ, DI_, D_);

    // 8) out = LN(out1 + tmp)
    add_ln_kernel<<<BQ, 256>>>(tmp, out1, ln2_g, ln2_b, out);
}

// round 16
// speedup vs baseline: 1.7511x; 1.1141x over previous
#include <cuda_runtime.h>
#include <cuda_bf16.h>
#include <math.h>
#include <stdint.h>

// Problem constants (fixed by the dataset)
#define B_  4
#define Q_  1024
#define D_  1024
#define N_  16
#define DH_ 64
#define DI_ 4096
#define BQ  (B_ * Q_)      // 4096
#define D3  (3 * D_)       // 3072

// ---------------- scratch (static device globals; no allocation) -------------
__device__ float g_heads[BQ * D3];   // 48 MB
__device__ float g_rk   [Q_ * D_];   //  4 MB
__device__ float g_av   [BQ * D_];   // 16 MB
__device__ float g_tmp  [BQ * D_];   // 16 MB
__device__ float g_out1 [BQ * D_];   // 16 MB
__device__ float g_ff1  [BQ * DI_];  // 64 MB

// fp16 fragment-major weight buffers (N/8 * K/16 tiles of 64 words)
__device__ uint32_t g_qkvw_h[(D3 / 8) * (D_ / 16) * 64];   // 6 MB
__device__ uint32_t g_rw_h  [(D_ / 8) * (D_ / 16) * 64];   // 2 MB
__device__ uint32_t g_ow_h  [(D_ / 8) * (D_ / 16) * 64];   // 2 MB
__device__ uint32_t g_f1w_h [(DI_ / 8) * (D_ / 16) * 64];  // 8 MB
__device__ uint32_t g_f2w_h [(D_ / 8) * (DI_ / 16) * 64];  // 8 MB

// ---------------- helpers ------------------------------------------------------
__device__ __forceinline__ uint32_t pk2h(float lo, float hi) {
    uint32_t r;
    asm("cvt.rn.f16x2.f32 %0, %2, %1;" : "=r"(r) : "f"(lo), "f"(hi));
    return r;
}
__device__ __forceinline__ void mma_f16(float* d, const uint32_t* a,
                                        const uint32_t* b) {
    asm volatile(
        "mma.sync.aligned.m16n8k16.row.col.f32.f16.f16.f32 "
        "{%0,%1,%2,%3}, {%4,%5,%6,%7}, {%8,%9}, {%0,%1,%2,%3};"
        : "+f"(d[0]), "+f"(d[1]), "+f"(d[2]), "+f"(d[3])
        : "r"(a[0]), "r"(a[1]), "r"(a[2]), "r"(a[3]), "r"(b[0]), "r"(b[1]));
}
__device__ __forceinline__ uint32_t smem_u32(const void* p) {
    uint32_t a;
    asm("{ .reg .u64 t; cvta.to.shared.u64 t, %1; cvt.u32.u64 %0, t; }"
        : "=r"(a) : "l"(p));
    return a;
}
__device__ __forceinline__ void cpa16(uint32_t dst, const void* src) {
    asm volatile("cp.async.ca.shared.global [%0], [%1], 16;"
                 :: "r"(dst), "l"(src));
}
#define CP_COMMIT() asm volatile("cp.async.commit_group;" ::: "memory")
__device__ __forceinline__ void cp_wait(int pending) {
    if (pending) asm volatile("cp.async.wait_group 1;" ::: "memory");
    else         asm volatile("cp.async.wait_group 0;" ::: "memory");
}

// ---- fp16 fragment-major smem addressing (kp = k-pair index) ----
__device__ __forceinline__ int ah_inner(int row, int kp) {
    int ld = ((row & 7) << 2) | (kp & 3);
    int e  = ((kp & 4) >> 1) | ((row & 8) >> 3);
    int f  = ld ^ (ld >> 3);
    return f * 4 + e;
}
// GEMM A (one ktile16 per chunk, 8 mtiles): kp 0..7
__device__ __forceinline__ int ah_word(int row, int kp) {
    return (row >> 4) * 128 + ah_inner(row, kp);
}
// attention B-op: 8 ntiles per ktile, stride 72, kp global 0..31
__device__ __forceinline__ int bw8h(int nn, int kp) {
    int ld = ((nn & 7) << 2) | (kp & 3);
    int e  = (kp & 4) >> 2;
    int h  = ld ^ (ld >> 3);
    return ((kp >> 3) * 8 + (nn >> 3)) * 72 + h * 2 + e;
}
// attention A-op (P): 4 mtiles per ktile, kp global 0..31
__device__ __forceinline__ int aw4h(int row, int kp) {
    return ((kp >> 3) * 4 + (row >> 4)) * 128 + ah_inner(row, kp & 7);
}

// ---------------- prep: fp32 row-major weights -> fp16 fragment-major ---------
// Output word idx: tile = kt*(N/8)+nt (64 words each); inner = h*2+e;
// inverse: ld = h^(h>>3); n = nt*8+(ld>>2); kp = (ld&3)|(e<<2); k = kt*16+kp*2.
__global__ void __launch_bounds__(256) prep_bh(
    const float* __restrict__ W, uint32_t* __restrict__ out, int N, int K)
{
    const int idx = blockIdx.x * 256 + threadIdx.x;
    const int total = (N >> 3) * (K >> 4) * 64;
    if (idx >= total) return;
    const int tile  = idx >> 6;
    const int inner = idx & 63;
    const int ntiles = N >> 3;
    const int kt = tile / ntiles;
    const int nt = tile - kt * ntiles;
    const int h  = inner >> 1;
    const int e  = inner & 1;
    const int ld = h ^ (h >> 3);
    const int nn = nt * 8 + (ld >> 2);
    const int k  = kt * 16 + (((ld & 3) | (e << 2)) << 1);
    const float* p = W + (size_t)nn * K + k;
    out[idx] = pk2h(p[0], p[1]);
}

// ---------------- fp16 HMMA GEMM: C = A @ Wfrag^T (+bias)(+relu) --------------
// 128x128 tile, BK=16, 256 threads (8 warps 4x2), warp tile 32x64.
// A: register-prefetch double buffer (fp32 LDG -> cvt -> STS frag-major).
// B: cp.async 3-stage ring straight from prepped fp16 fragment buffer.
template<bool BIAS, bool RELU>
__global__ void __launch_bounds__(256, 2) gemm_mma(
    const float* __restrict__ A, const uint32_t* __restrict__ Bp,
    const float* __restrict__ bias, float* __restrict__ C,
    int M, int K, int ldc)
{
    __shared__ uint32_t sAh[2][1024];
    __shared__ uint32_t sB[3][1024];

    const int t    = threadIdx.x;
    const int m0   = blockIdx.y * 128;
    const int n0   = blockIdx.x * 128;
    const int lane = t & 31;
    const int w    = t >> 5;
    const int g    = lane >> 2;
    const int t4   = lane & 3;
    const int wm   = (w >> 1) * 32;
    const int wn   = (w & 1) * 64;
    const int mt0  = (w >> 1) * 2;
    const int nt0  = (w & 1) * 8;
    const int fl   = lane ^ (lane >> 3);
    const int lrow = t >> 1;
    const int lkq  = (t & 1) * 8;
    const int NC   = K >> 4;
    const int ntg  = ldc >> 3;          // global ntiles per ktile

    const float* Ap = A + (size_t)(m0 + lrow) * K + lkq;
    const uint32_t* Bbase = Bp + (size_t)(n0 >> 3) * 64 + t * 4;
    const uint32_t sBaddr = smem_u32(&sB[0][0]);

    float acc[2][8][4];
    #pragma unroll
    for (int mt = 0; mt < 2; mt++)
        #pragma unroll
        for (int nt = 0; nt < 8; nt++)
            #pragma unroll
            for (int e = 0; e < 4; e++) acc[mt][nt][e] = 0.f;

    auto issueB = [&](int stage, int c) {
        cpa16(sBaddr + stage * 4096 + t * 16, Bbase + (size_t)c * ntg * 64);
        CP_COMMIT();
    };

    float4 pa0 = *(const float4*)Ap;
    float4 pa1 = *(const float4*)(Ap + 4);

    auto stsA = [&](int bf_, float4 a0, float4 a1) {
        float va[8] = {a0.x, a0.y, a0.z, a0.w, a1.x, a1.y, a1.z, a1.w};
        const int kpb = lkq >> 1;
        #pragma unroll
        for (int u = 0; u < 4; u++)
            sAh[bf_][ah_word(lrow, kpb + u)] = pk2h(va[2 * u], va[2 * u + 1]);
    };

    // ---- prologue ----
    issueB(0, 0);
    if (NC > 1) issueB(1, 1);
    stsA(0, pa0, pa1);
    cp_wait(NC > 1);        // stage 0 ready
    __syncthreads();

    int abuf = 0, bst = 0;
    for (int c = 0; c < NC; c++) {
        const bool hn = (c + 1 < NC);
        if (hn) {
            pa0 = *(const float4*)(Ap + (c + 1) * 16);
            pa1 = *(const float4*)(Ap + (c + 1) * 16 + 4);
        }

        {
            uint4 af[2];
            uint2 bfr[8];
            #pragma unroll
            for (int mt = 0; mt < 2; mt++)
                af[mt] = *(const uint4*)&sAh[abuf][(mt0 + mt) * 128 + fl * 4];
            #pragma unroll
            for (int nt = 0; nt < 8; nt++)
                bfr[nt] = *(const uint2*)&sB[bst][(nt0 + nt) * 64 + fl * 2];
            #pragma unroll
            for (int mt = 0; mt < 2; mt++)
                #pragma unroll
                for (int nt = 0; nt < 8; nt++)
                    mma_f16(acc[mt][nt], (const uint32_t*)&af[mt],
                            (const uint32_t*)&bfr[nt]);
        }

        if (hn) {
            const int bnext = bst + 1 == 3 ? 0 : bst + 1;
            if (c + 2 < NC) {
                const int b2 = bnext + 1 == 3 ? 0 : bnext + 1;
                issueB(b2, c + 2);
            }
            abuf ^= 1;
            stsA(abuf, pa0, pa1);
            cp_wait(c + 2 < NC);     // stage c+1 ready
            __syncthreads();
            bst = bnext;
        }
    }

    // ---- epilogue ----
    #pragma unroll
    for (int mt = 0; mt < 2; mt++) {
        const int row = m0 + wm + mt * 16 + g;
        #pragma unroll
        for (int nt = 0; nt < 8; nt++) {
            const int col = n0 + wn + nt * 8 + 2 * t4;
            float b0v = BIAS ? bias[col]     : 0.f;
            float b1v = BIAS ? bias[col + 1] : 0.f;
            float x0 = acc[mt][nt][0] + b0v;
            float x1 = acc[mt][nt][1] + b1v;
            float x2 = acc[mt][nt][2] + b0v;
            float x3 = acc[mt][nt][3] + b1v;
            if (RELU) {
                x0 = fmaxf(x0, 0.f); x1 = fmaxf(x1, 0.f);
                x2 = fmaxf(x2, 0.f); x3 = fmaxf(x3, 0.f);
            }
            *(float2*)&C[(size_t)row * ldc + col]       = make_float2(x0, x1);
            *(float2*)&C[(size_t)(row + 8) * ldc + col] = make_float2(x2, x3);
        }
    }
}

// ---------------- fp16 MMA flash attention with rolling-band BD ----------------
#define RSTR 197
#define ATT_WORDS (2304 + 2304 + 4608 + 64 * RSTR + 2048 + 256)
#define ATT_SMEM  (ATT_WORDS * 4)

__global__ void __launch_bounds__(256, 1) attn_mma(
    const float* __restrict__ heads, const float* __restrict__ rk,
    const float* __restrict__ rwb, const float* __restrict__ rrb,
    float* __restrict__ av)
{
    extern __shared__ uint32_t smw[];
    uint32_t* sK    = smw;
    uint32_t* sV    = sK + 2304;
    uint32_t* sBseg = sV + 2304;
    float*    ring  = (float*)(sBseg + 4608);
    uint32_t* sP    = (uint32_t*)(ring + 64 * RSTR);
    float*    red   = (float*)(sP + 2048);

    const int i0   = (gridDim.x - 1 - blockIdx.x) * 64;
    const int n    = blockIdx.y;
    const int b    = blockIdx.z;
    const int t    = threadIdx.x;
    const int lane = t & 31;
    const int w    = t >> 5;
    const int wr   = w & 3;
    const int wc   = w >> 2;
    const int g    = lane >> 2;
    const int t4   = lane & 3;
    const int fl   = lane ^ (lane >> 3);

    const int di0 = wr * 16 + g;
    const int di1 = di0 + 8;

    uint32_t qw[4][4], qr[4][4];
    {
        const float* qb = heads + (size_t)(b * Q_ + i0 + di0) * D3 + n * DH_;
        const float* wb_ = rwb + n * DH_;
        const float* rb_ = rrb + n * DH_;
        #pragma unroll
        for (int kt = 0; kt < 4; kt++) {
            const int cl = kt * 16 + 2 * t4;
            const int ch = cl + 8;
            float2 ql0 = *(const float2*)(qb + cl);
            float2 qh0 = *(const float2*)(qb + ch);
            float2 ql1 = *(const float2*)(qb + 8 * D3 + cl);
            float2 qh1 = *(const float2*)(qb + 8 * D3 + ch);
            float2 wl = *(const float2*)(wb_ + cl);
            float2 wh = *(const float2*)(wb_ + ch);
            float2 rl = *(const float2*)(rb_ + cl);
            float2 rh = *(const float2*)(rb_ + ch);
            qw[kt][0] = pk2h(ql0.x + wl.x, ql0.y + wl.y);
            qw[kt][1] = pk2h(ql1.x + wl.x, ql1.y + wl.y);
            qw[kt][2] = pk2h(qh0.x + wh.x, qh0.y + wh.y);
            qw[kt][3] = pk2h(qh1.x + wh.x, qh1.y + wh.y);
            qr[kt][0] = pk2h(ql0.x + rl.x, ql0.y + rl.y);
            qr[kt][1] = pk2h(ql1.x + rl.x, ql1.y + rl.y);
            qr[kt][2] = pk2h(qh0.x + rh.x, qh0.y + rh.y);
            qr[kt][3] = pk2h(qh1.x + rh.x, qh1.y + rh.y);
        }
    }

    float O[4][4];
    #pragma unroll
    for (int nt = 0; nt < 4; nt++)
        #pragma unroll
        for (int e = 0; e < 4; e++) O[nt][e] = 0.f;
    float m0r = -1e30f, m1r = -1e30f, l0r = 0.f, l1r = 0.f;

    const int gbase0 = Q_ - 64 - i0;
    int rb0 = 63 - di0;
    int rb1 = 63 - di1;
    int wb  = 63;

    for (int j0 = 0; j0 <= i0; j0 += 64) {
        __syncthreads();

        {
            const int jrow = t >> 2, d0 = (t & 3) * 16;
            const float* kp_ = heads + (size_t)(b * Q_ + j0 + jrow) * D3 + D_ + n * DH_ + d0;
            #pragma unroll
            for (int u = 0; u < 16; u += 4) {
                float4 kv = *(const float4*)(kp_ + u);
                const int kp = (d0 + u) >> 1;
                sK[bw8h(jrow, kp)]     = pk2h(kv.x, kv.y);
                sK[bw8h(jrow, kp + 1)] = pk2h(kv.z, kv.w);
            }
        }
        {
            const int jp = t >> 3;
            const int d0 = (t & 7) * 8;
            const float* v0 = heads + (size_t)(b * Q_ + j0 + 2 * jp) * D3 + 2 * D_ + n * DH_ + d0;
            const float* v1 = v0 + D3;
            float4 x0 = *(const float4*)v0;
            float4 x1 = *(const float4*)(v0 + 4);
            float4 y0 = *(const float4*)v1;
            float4 y1 = *(const float4*)(v1 + 4);
            float va[8] = {x0.x, x0.y, x0.z, x0.w, x1.x, x1.y, x1.z, x1.w};
            float vb[8] = {y0.x, y0.y, y0.z, y0.w, y1.x, y1.y, y1.z, y1.w};
            #pragma unroll
            for (int u = 0; u < 8; u++)
                sV[bw8h(d0 + u, jp)] = pk2h(va[u], vb[u]);
        }
        if (j0 == 0) {
            const int s = t >> 1, d0 = (t & 1) * 32;
            int grow = gbase0 + s;
            if (grow > Q_ - 1) grow = Q_ - 1;
            const float* rp = rk + (size_t)grow * D_ + n * DH_ + d0;
            uint32_t* dst = sBseg + (s >> 6) * 2304;
            const int sr = s & 63;
            #pragma unroll
            for (int u = 0; u < 32; u += 4) {
                float4 rv = *(const float4*)(rp + u);
                const int kp = (d0 + u) >> 1;
                dst[bw8h(sr, kp)]     = pk2h(rv.x, rv.y);
                dst[bw8h(sr, kp + 1)] = pk2h(rv.z, rv.w);
            }
        } else {
            const int s = t >> 2, d0 = (t & 3) * 16;
            int grow = gbase0 + j0 + 63 + s;
            if (grow > Q_ - 1) grow = Q_ - 1;
            const float* rp = rk + (size_t)grow * D_ + n * DH_ + d0;
            #pragma unroll
            for (int u = 0; u < 16; u += 4) {
                float4 rv = *(const float4*)(rp + u);
                const int kp = (d0 + u) >> 1;
                sBseg[bw8h(s, kp)]     = pk2h(rv.x, rv.y);
                sBseg[bw8h(s, kp + 1)] = pk2h(rv.z, rv.w);
            }
        }
        __syncthreads();

        {
            const int nseg = (j0 == 0) ? 2 : 1;
            for (int sg = 0; sg < nseg; sg++) {
                float bd[4][4];
                #pragma unroll
                for (int nt = 0; nt < 4; nt++)
                    #pragma unroll
                    for (int e = 0; e < 4; e++) bd[nt][e] = 0.f;
                #pragma unroll
                for (int kt = 0; kt < 4; kt++) {
                    uint2 bf[4];
                    #pragma unroll
                    for (int nt = 0; nt < 4; nt++)
                        bf[nt] = *(const uint2*)
                            &sBseg[sg * 2304 + (kt * 8 + wc * 4 + nt) * 72 + fl * 2];
                    #pragma unroll
                    for (int nt = 0; nt < 4; nt++)
                        mma_f16(bd[nt], qr[kt], (const uint32_t*)&bf[nt]);
                }
                #pragma unroll
                for (int nt = 0; nt < 4; nt++) {
                    int c0;
                    if (j0 == 0) {
                        c0 = sg * 64 + wc * 32 + nt * 8 + 2 * t4;
                    } else {
                        c0 = wb + wc * 32 + nt * 8 + 2 * t4;
                        if (c0 >= 192) c0 -= 192;
                    }
                    int c1 = c0 + 1; if (c1 >= 192) c1 -= 192;
                    ring[di0 * RSTR + c0] = bd[nt][0];
                    ring[di0 * RSTR + c1] = bd[nt][1];
                    ring[di1 * RSTR + c0] = bd[nt][2];
                    ring[di1 * RSTR + c1] = bd[nt][3];
                }
            }
        }
        __syncthreads();

        float p[4][4];
        {
            float ac[4][4];
            #pragma unroll
            for (int nt = 0; nt < 4; nt++)
                #pragma unroll
                for (int e = 0; e < 4; e++) ac[nt][e] = 0.f;
            #pragma unroll
            for (int kt = 0; kt < 4; kt++) {
                uint2 kf[4];
                #pragma unroll
                for (int nt = 0; nt < 4; nt++)
                    kf[nt] = *(const uint2*)&sK[(kt * 8 + wc * 4 + nt) * 72 + fl * 2];
                #pragma unroll
                for (int nt = 0; nt < 4; nt++)
                    mma_f16(ac[nt], qw[kt], (const uint32_t*)&kf[nt]);
            }
            const bool diag = (j0 == i0);
            #pragma unroll
            for (int nt = 0; nt < 4; nt++) {
                const int dj = wc * 32 + nt * 8 + 2 * t4;
                int x0 = rb0 + dj;     if (x0 >= 192) x0 -= 192;
                int x0b = x0 + 1;      if (x0b >= 192) x0b -= 192;
                int x1 = rb1 + dj;     if (x1 >= 192) x1 -= 192;
                int x1b = x1 + 1;      if (x1b >= 192) x1b -= 192;
                float v00 = (ac[nt][0] + ring[di0 * RSTR + x0])  * 0.125f;
                float v01 = (ac[nt][1] + ring[di0 * RSTR + x0b]) * 0.125f;
                float v10 = (ac[nt][2] + ring[di1 * RSTR + x1])  * 0.125f;
                float v11 = (ac[nt][3] + ring[di1 * RSTR + x1b]) * 0.125f;
                if (diag) {
                    if (dj     > di0) v00 = -1e30f;
                    if (dj + 1 > di0) v01 = -1e30f;
                    if (dj     > di1) v10 = -1e30f;
                    if (dj + 1 > di1) v11 = -1e30f;
                }
                p[nt][0] = v00; p[nt][1] = v01; p[nt][2] = v10; p[nt][3] = v11;
            }
        }

        {
            float mx0 = -1e30f, mx1 = -1e30f;
            #pragma unroll
            for (int nt = 0; nt < 4; nt++) {
                mx0 = fmaxf(mx0, fmaxf(p[nt][0], p[nt][1]));
                mx1 = fmaxf(mx1, fmaxf(p[nt][2], p[nt][3]));
            }
            mx0 = fmaxf(mx0, __shfl_xor_sync(0xffffffffu, mx0, 1));
            mx0 = fmaxf(mx0, __shfl_xor_sync(0xffffffffu, mx0, 2));
            mx1 = fmaxf(mx1, __shfl_xor_sync(0xffffffffu, mx1, 1));
            mx1 = fmaxf(mx1, __shfl_xor_sync(0xffffffffu, mx1, 2));
            if (t4 == 0) {
                red[wc * 64 + di0] = mx0;
                red[wc * 64 + di1] = mx1;
            }
        }
        __syncthreads();

        const float mn0 = fmaxf(m0r, fmaxf(red[di0], red[64 + di0]));
        const float mn1 = fmaxf(m1r, fmaxf(red[di1], red[64 + di1]));
        const float fac0 = __expf(m0r - mn0);
        const float fac1 = __expf(m1r - mn1);
        m0r = mn0; m1r = mn1;

        {
            float s0 = 0.f, s1 = 0.f;
            #pragma unroll
            for (int nt = 0; nt < 4; nt++) {
                p[nt][0] = __expf(p[nt][0] - mn0);
                p[nt][1] = __expf(p[nt][1] - mn0);
                p[nt][2] = __expf(p[nt][2] - mn1);
                p[nt][3] = __expf(p[nt][3] - mn1);
                s0 += p[nt][0] + p[nt][1];
                s1 += p[nt][2] + p[nt][3];
            }
            s0 += __shfl_xor_sync(0xffffffffu, s0, 1);
            s0 += __shfl_xor_sync(0xffffffffu, s0, 2);
            s1 += __shfl_xor_sync(0xffffffffu, s1, 1);
            s1 += __shfl_xor_sync(0xffffffffu, s1, 2);
            if (t4 == 0) {
                red[128 + wc * 64 + di0] = s0;
                red[128 + wc * 64 + di1] = s1;
            }
        }
        __syncthreads();

        l0r = l0r * fac0 + red[128 + di0] + red[128 + 64 + di0];
        l1r = l1r * fac1 + red[128 + di1] + red[128 + 64 + di1];
        #pragma unroll
        for (int nt = 0; nt < 4; nt++) {
            O[nt][0] *= fac0; O[nt][1] *= fac0;
            O[nt][2] *= fac1; O[nt][3] *= fac1;
        }

        #pragma unroll
        for (int nt = 0; nt < 4; nt++) {
            const int dj = wc * 32 + nt * 8 + 2 * t4;
            const int kp = dj >> 1;
            sP[aw4h(di0, kp)] = pk2h(p[nt][0], p[nt][1]);
            sP[aw4h(di1, kp)] = pk2h(p[nt][2], p[nt][3]);
        }
        __syncthreads();

        #pragma unroll
        for (int kt = 0; kt < 4; kt++) {
            uint4 af = *(const uint4*)&sP[(kt * 4 + wr) * 128 + fl * 4];
            uint2 vf[4];
            #pragma unroll
            for (int nt = 0; nt < 4; nt++)
                vf[nt] = *(const uint2*)&sV[(kt * 8 + wc * 4 + nt) * 72 + fl * 2];
            #pragma unroll
            for (int nt = 0; nt < 4; nt++)
                mma_f16(O[nt], (const uint32_t*)&af, (const uint32_t*)&vf[nt]);
        }

        rb0 += 64; if (rb0 >= 192) rb0 -= 192;
        rb1 += 64; if (rb1 >= 192) rb1 -= 192;
        if (j0 == 0) wb = 127;
        else { wb += 64; if (wb >= 192) wb -= 192; }
    }

    const float inv0 = 1.f / l0r;
    const float inv1 = 1.f / l1r;
    #pragma unroll
    for (int nt = 0; nt < 4; nt++) {
        const int col = n * DH_ + wc * 32 + nt * 8 + 2 * t4;
        *(float2*)&av[(size_t)(b * Q_ + i0 + di0) * D_ + col] =
            make_float2(O[nt][0] * inv0, O[nt][1] * inv0);
        *(float2*)&av[(size_t)(b * Q_ + i0 + di1) * D_ + col] =
            make_float2(O[nt][2] * inv1, O[nt][3] * inv1);
    }
}

// ---------------- fused residual add + LayerNorm (shuffle reductions) ---------
__global__ void __launch_bounds__(256) add_ln_kernel(
    const float* __restrict__ x, const float* __restrict__ resid,
    const float* __restrict__ g, const float* __restrict__ bta,
    float* __restrict__ out)
{
    const int row = blockIdx.x;
    const int t = threadIdx.x;
    const int lane = t & 31;
    const int wid = t >> 5;
    __shared__ float red[8];
    __shared__ float bcast[2];

    float v[4];
    float s = 0.f;
    #pragma unroll
    for (int u = 0; u < 4; u++) {
        int c = t + u * 256;
        v[u] = x[(size_t)row * D_ + c] + resid[(size_t)row * D_ + c];
        s += v[u];
    }
    #pragma unroll
    for (int o = 16; o > 0; o >>= 1) s += __shfl_xor_sync(0xffffffffu, s, o);
    if (lane == 0) red[wid] = s;
    __syncthreads();
    if (t == 0) {
        float acc = 0.f;
        #pragma unroll
        for (int i = 0; i < 8; i++) acc += red[i];
        bcast[0] = acc * (1.f / D_);
    }
    __syncthreads();
    const float mean = bcast[0];

    s = 0.f;
    #pragma unroll
    for (int u = 0; u < 4; u++) {
        float dd = v[u] - mean;
        s += dd * dd;
    }
    #pragma unroll
    for (int o = 16; o > 0; o >>= 1) s += __shfl_xor_sync(0xffffffffu, s, o);
    if (lane == 0) red[wid] = s;
    __syncthreads();
    if (t == 0) {
        float acc = 0.f;
        #pragma unroll
        for (int i = 0; i < 8; i++) acc += red[i];
        bcast[1] = rsqrtf(acc * (1.f / D_) + 1e-5f);
    }
    __syncthreads();
    const float rstd = bcast[1];

    #pragma unroll
    for (int u = 0; u < 4; u++) {
        int c = t + u * 256;
        out[(size_t)row * D_ + c] = (v[u] - mean) * rstd * g[c] + bta[c];
    }
}

// ---------------- host launch -------------------------------------------------
extern "C" void kernel_launch(void* const* d_in, const int* in_sizes, int n_in,
                              void* d_out, int out_size)
{
    const float* w     = (const float*)d_in[0];
    const float* r     = (const float*)d_in[1];
    const float* qkv_w = (const float*)d_in[3];
    const float* r_w   = (const float*)d_in[4];
    const float* o_w   = (const float*)d_in[5];
    const float* rwb   = (const float*)d_in[6];
    const float* rrb   = (const float*)d_in[7];
    const float* ln1_g = (const float*)d_in[8];
    const float* ln1_b = (const float*)d_in[9];
    const float* ff_w1 = (const float*)d_in[10];
    const float* ff_b1 = (const float*)d_in[11];
    const float* ff_w2 = (const float*)d_in[12];
    const float* ff_b2 = (const float*)d_in[13];
    const float* ln2_g = (const float*)d_in[14];
    const float* ln2_b = (const float*)d_in[15];
    float* out = (float*)d_out;

    float *heads, *rk, *av, *tmp, *out1, *ff1;
    cudaGetSymbolAddress((void**)&heads, g_heads);
    cudaGetSymbolAddress((void**)&rk,    g_rk);
    cudaGetSymbolAddress((void**)&av,    g_av);
    cudaGetSymbolAddress((void**)&tmp,   g_tmp);
    cudaGetSymbolAddress((void**)&out1,  g_out1);
    cudaGetSymbolAddress((void**)&ff1,   g_ff1);

    uint32_t *qkvw_h, *rw_h, *ow_h, *f1w_h, *f2w_h;
    cudaGetSymbolAddress((void**)&qkvw_h, g_qkvw_h);
    cudaGetSymbolAddress((void**)&rw_h,   g_rw_h);
    cudaGetSymbolAddress((void**)&ow_h,   g_ow_h);
    cudaGetSymbolAddress((void**)&f1w_h,  g_f1w_h);
    cudaGetSymbolAddress((void**)&f2w_h,  g_f2w_h);

    cudaFuncSetAttribute(attn_mma,
        cudaFuncAttributeMaxDynamicSharedMemorySize, ATT_SMEM);

    // ---- weight prep (fp16 fragment-major) ----
    prep_bh<<<(D3 / 8) * (D_ / 16) * 64 / 256, 256>>>(qkv_w, qkvw_h, D3, D_);
    prep_bh<<<(D_ / 8) * (D_ / 16) * 64 / 256, 256>>>(r_w,   rw_h,   D_, D_);
    prep_bh<<<(D_ / 8) * (D_ / 16) * 64 / 256, 256>>>(o_w,   ow_h,   D_, D_);
    prep_bh<<<(DI_ / 8) * (D_ / 16) * 64 / 256, 256>>>(ff_w1, f1w_h, DI_, D_);
    prep_bh<<<(D_ / 8) * (DI_ / 16) * 64 / 256, 256>>>(ff_w2, f2w_h, D_, DI_);

    // 1) QKV projection                                   [4096, 3072]
    gemm_mma<false, false><<<dim3(D3 / 128, BQ / 128), 256>>>(
        w, qkvw_h, nullptr, heads, BQ, D_, D3);

    // 2) rk = r @ r_w^T                                   [1024, 1024]
    gemm_mma<false, false><<<dim3(D_ / 128, Q_ / 128), 256>>>(
        r, rw_h, nullptr, rk, Q_, D_, D_);

    // 3) fp16 MMA flash attention (rolling-band BD)       av [4096, 1024]
    attn_mma<<<dim3(Q_ / 64, N_, B_), 256, ATT_SMEM>>>(
        heads, rk, rwb, rrb, av);

    // 4) O projection                                     [4096, 1024]
    gemm_mma<false, false><<<dim3(D_ / 128, BQ / 128), 256>>>(
        av, ow_h, nullptr, tmp, BQ, D_, D_);

    // 5) out1 = LN(w + tmp)
    add_ln_kernel<<<BQ, 256>>>(tmp, w, ln1_g, ln1_b, out1);

    // 6) ff1 = relu(out1 @ ff_w1^T + b1)                  [4096, 4096]
    gemm_mma<true, true><<<dim3(DI_ / 128, BQ / 128), 256>>>(
        out1, f1w_h, ff_b1, ff1, BQ, D_, DI_);

    // 7) tmp = ff1 @ ff_w2^T + b2                         [4096, 1024]
    gemm_mma<true, false><<<dim3(D_ / 128, BQ / 128), 256>>>(
        ff1, f2w_h, ff_b2, tmp, BQ, DI_, D_);

    // 8) out = LN(out1 + tmp)
    add_ln_kernel<<<BQ, 256>>>(tmp, out1, ln2_g, ln2_b, out);
}